// round 1
// baseline (speedup 1.0000x reference)
#include <cuda_runtime.h>
#include <cuda_bf16.h>

// ---------------------------------------------------------------------------
// QwenAttention: hidden[2048,2048] -> out[2048,2048]
//   qkv = hidden @ W_attn            [2048,3072]
//   rope(q cols 0..2047, k cols 2048..2559)
//   flash attention (16 heads, GQA kv = h/4, causal)  -> attn [2048,2048]
//   out = attn @ W_proj
// ---------------------------------------------------------------------------

#define S_LEN   2048
#define HIDDEN  2048
#define QKV_LD  3072
#define N_HEADS 16

__device__ float g_qkv[S_LEN * QKV_LD];     // 25.2 MB scratch
__device__ float g_attn[S_LEN * HIDDEN];    // 16.8 MB scratch

// ---------------------------------------------------------------------------
// fp32 SGEMM: C[M,N] = A[M,K] @ B[K,N], M=K=2048 fixed, N in {3072,2048}
// BM=BN=128, BK=16, 256 threads, 8x8 micro-tile.
// ---------------------------------------------------------------------------
__global__ __launch_bounds__(256) void sgemm128(
    const float* __restrict__ A, const float* __restrict__ B,
    float* __restrict__ C, int N)
{
    const int K = 2048;
    __shared__ float As[16][132];   // As[kk][m], padded
    __shared__ float Bs[16][128];   // Bs[kk][n]

    int tid = threadIdx.x;
    int tx = tid & 15;        // 0..15 -> 8 cols each
    int ty = tid >> 4;        // 0..15 -> 8 rows each
    int row0 = blockIdx.y * 128;
    int col0 = blockIdx.x * 128;

    int a_row = tid >> 2;            // 0..63
    int a_col = (tid & 3) * 4;       // 0,4,8,12
    int b_row = tid >> 5;            // 0..7
    int b_col = (tid & 31) * 4;      // 0..124

    float acc[8][8];
#pragma unroll
    for (int i = 0; i < 8; i++)
#pragma unroll
        for (int j = 0; j < 8; j++) acc[i][j] = 0.f;

    for (int k0 = 0; k0 < K; k0 += 16) {
        float4 a0 = *(const float4*)&A[(row0 + a_row) * K + k0 + a_col];
        float4 a1 = *(const float4*)&A[(row0 + a_row + 64) * K + k0 + a_col];
        As[a_col + 0][a_row] = a0.x;
        As[a_col + 1][a_row] = a0.y;
        As[a_col + 2][a_row] = a0.z;
        As[a_col + 3][a_row] = a0.w;
        As[a_col + 0][a_row + 64] = a1.x;
        As[a_col + 1][a_row + 64] = a1.y;
        As[a_col + 2][a_row + 64] = a1.z;
        As[a_col + 3][a_row + 64] = a1.w;
        *(float4*)&Bs[b_row][b_col]     = *(const float4*)&B[(k0 + b_row) * N + col0 + b_col];
        *(float4*)&Bs[b_row + 8][b_col] = *(const float4*)&B[(k0 + b_row + 8) * N + col0 + b_col];
        __syncthreads();

#pragma unroll
        for (int kk = 0; kk < 16; kk++) {
            float a[8], b[8];
            *(float4*)&a[0] = *(float4*)&As[kk][ty * 8];
            *(float4*)&a[4] = *(float4*)&As[kk][ty * 8 + 4];
            *(float4*)&b[0] = *(float4*)&Bs[kk][tx * 8];
            *(float4*)&b[4] = *(float4*)&Bs[kk][tx * 8 + 4];
#pragma unroll
            for (int i = 0; i < 8; i++)
#pragma unroll
                for (int j = 0; j < 8; j++)
                    acc[i][j] = fmaf(a[i], b[j], acc[i][j]);
        }
        __syncthreads();
    }

#pragma unroll
    for (int i = 0; i < 8; i++) {
        float4 c0 = make_float4(acc[i][0], acc[i][1], acc[i][2], acc[i][3]);
        float4 c1 = make_float4(acc[i][4], acc[i][5], acc[i][6], acc[i][7]);
        float* cp = &C[(row0 + ty * 8 + i) * N + col0 + tx * 8];
        *(float4*)cp       = c0;
        *(float4*)(cp + 4) = c1;
    }
}

// ---------------------------------------------------------------------------
// RoPE (faithful to reference: emb = cat(sin f, cos f); use cos(emb), sin(emb))
// Applied in-place to Q (16 heads) and K (4 heads) columns of g_qkv.
// idx -> (s, head 0..19, i 0..63)
// ---------------------------------------------------------------------------
__global__ __launch_bounds__(256) void rope_kernel(float* __restrict__ qkv)
{
    int idx = blockIdx.x * 256 + threadIdx.x;
    int i  = idx & 63;
    int hh = (idx >> 6) % 20;
    int s  = idx / (64 * 20);

    int col = (hh < 16) ? hh * 128 : 2048 + (hh - 16) * 128;
    float* p = qkv + s * QKV_LD + col;

    // inv_freq = 10000^(-i/64) = exp(-i * ln(1e4)/64)
    float f = (float)s * __expf((float)i * -0.14391156831212787f);
    float sf = sinf(f);
    float cf = cosf(f);

    float x1 = p[i];
    float x2 = p[i + 64];
    // d<64:  q' = q*cos(sin f) - q[d+64]*sin(sin f)
    // d>=64: q' = q*cos(cos f) + q[d-64]*sin(cos f)
    p[i]      = x1 * cosf(sf) - x2 * sinf(sf);
    p[i + 64] = x2 * cosf(cf) + x1 * sinf(cf);
}

// ---------------------------------------------------------------------------
// Flash attention (causal), BM=BN=64, D=128, 128 threads.
// Thread t owns q-row r = t>>1, output half dhalf = (t&1)*64, and score
// columns cb = (t&1)*32 .. +31 (partner exchange via shfl xor 1).
// ---------------------------------------------------------------------------
#define FLASH_SMEM ((64 * 132 + 64 * 128 + 64 * 128) * 4)

__global__ __launch_bounds__(128) void flash_kernel(
    const float* __restrict__ qkv, float* __restrict__ attn)
{
    extern __shared__ float sm[];
    float* sQ = sm;                       // [64][132]
    float* sK = sQ + 64 * 132;            // [64][128]
    float* sV = sK + 64 * 128;            // [64][128]

    const int h  = blockIdx.y;
    const int qb = blockIdx.x;
    const int q0 = qb * 64;
    const int kvh = h >> 2;
    const int t = threadIdx.x;

    // load Q tile (rows q0..q0+63, cols h*128..+127)
    for (int i = t; i < 64 * 32; i += 128) {
        int row = i >> 5, d4 = (i & 31) * 4;
        *(float4*)&sQ[row * 132 + d4] =
            *(const float4*)&qkv[(q0 + row) * QKV_LD + h * 128 + d4];
    }

    const int r  = t >> 1;
    const int cb = (t & 1) * 32;
    const int dhalf = (t & 1) * 64;

    float m_old = -1e30f, l = 0.f;
    float acc[64];
#pragma unroll
    for (int d = 0; d < 64; d++) acc[d] = 0.f;

    const float scale = 0.08838834764831845f;   // 128^-0.5

    for (int j = 0; j <= qb; j++) {
        int k0 = j * 64;
        __syncthreads();   // protect sK/sV from previous iter readers
        for (int i = t; i < 64 * 32; i += 128) {
            int row = i >> 5, d4 = (i & 31) * 4;
            const float* src = &qkv[(k0 + row) * QKV_LD + 2048 + kvh * 128 + d4];
            *(float4*)&sK[row * 128 + d4] = *(const float4*)src;
            *(float4*)&sV[row * 128 + d4] = *(const float4*)(src + 512);
        }
        __syncthreads();

        // scores: s_reg[c] = dot(Q[r], K[cb+c]) * scale
        float s_reg[32];
#pragma unroll
        for (int c = 0; c < 32; c++) s_reg[c] = 0.f;

        for (int kk = 0; kk < 128; kk += 4) {
            float4 q4 = *(float4*)&sQ[r * 132 + kk];
#pragma unroll
            for (int c = 0; c < 32; c++) {
                float4 k4 = *(float4*)&sK[(cb + c) * 128 + kk];
                s_reg[c] = fmaf(q4.x, k4.x, s_reg[c]);
                s_reg[c] = fmaf(q4.y, k4.y, s_reg[c]);
                s_reg[c] = fmaf(q4.z, k4.z, s_reg[c]);
                s_reg[c] = fmaf(q4.w, k4.w, s_reg[c]);
            }
        }

        bool diag = (j == qb);
#pragma unroll
        for (int c = 0; c < 32; c++) {
            float sv = s_reg[c] * scale;
            if (diag && (cb + c > r)) sv = -1e30f;
            s_reg[c] = sv;
        }

        // online softmax
        float mt = -1e30f;
#pragma unroll
        for (int c = 0; c < 32; c++) mt = fmaxf(mt, s_reg[c]);
        mt = fmaxf(mt, __shfl_xor_sync(0xffffffffu, mt, 1));
        float m_new = fmaxf(m_old, mt);

        float lt = 0.f;
#pragma unroll
        for (int c = 0; c < 32; c++) {
            float p = __expf(s_reg[c] - m_new);
            s_reg[c] = p;
            lt += p;
        }
        lt += __shfl_xor_sync(0xffffffffu, lt, 1);

        float alpha = __expf(m_old - m_new);
        l = l * alpha + lt;
        m_old = m_new;
#pragma unroll
        for (int d = 0; d < 64; d++) acc[d] *= alpha;

        // PV: each thread covers all 64 columns via partner P exchange
        for (int ci = 0; ci < 32; ci++) {
            float p  = s_reg[ci];
            float po = __shfl_xor_sync(0xffffffffu, p, 1);
            int c1 = cb + ci;
            int c2 = (cb ^ 32) + ci;
            const float* v1 = &sV[c1 * 128 + dhalf];
            const float* v2 = &sV[c2 * 128 + dhalf];
#pragma unroll
            for (int dd = 0; dd < 64; dd += 4) {
                float4 a4 = *(const float4*)(v1 + dd);
                float4 b4 = *(const float4*)(v2 + dd);
                acc[dd + 0] = fmaf(p, a4.x, fmaf(po, b4.x, acc[dd + 0]));
                acc[dd + 1] = fmaf(p, a4.y, fmaf(po, b4.y, acc[dd + 1]));
                acc[dd + 2] = fmaf(p, a4.z, fmaf(po, b4.z, acc[dd + 2]));
                acc[dd + 3] = fmaf(p, a4.w, fmaf(po, b4.w, acc[dd + 3]));
            }
        }
    }

    float inv = 1.f / l;
    float* op = &attn[(q0 + r) * HIDDEN + h * 128 + dhalf];
#pragma unroll
    for (int dd = 0; dd < 64; dd += 4) {
        float4 o4 = make_float4(acc[dd] * inv, acc[dd + 1] * inv,
                                acc[dd + 2] * inv, acc[dd + 3] * inv);
        *(float4*)(op + dd) = o4;
    }
}

// ---------------------------------------------------------------------------
extern "C" void kernel_launch(void* const* d_in, const int* in_sizes, int n_in,
                              void* d_out, int out_size)
{
    const float* hidden = (const float*)d_in[0];
    // d_in[1] = attention_mask (pure causal additive; applied structurally)
    // d_in[2] = position_ids   (arange; applied structurally)
    const float* W_attn = (const float*)d_in[3];
    const float* W_proj = (const float*)d_in[4];
    float* out = (float*)d_out;

    float *qkv, *attn;
    cudaGetSymbolAddress((void**)&qkv, g_qkv);
    cudaGetSymbolAddress((void**)&attn, g_attn);

    // 1) qkv = hidden @ W_attn   [2048,3072]
    sgemm128<<<dim3(QKV_LD / 128, S_LEN / 128), 256>>>(hidden, W_attn, qkv, QKV_LD);

    // 2) RoPE in place on q,k
    rope_kernel<<<(S_LEN * 20 * 64) / 256, 256>>>(qkv);

    // 3) flash attention -> attn [2048,2048]
    cudaFuncSetAttribute(flash_kernel, cudaFuncAttributeMaxDynamicSharedMemorySize,
                         FLASH_SMEM);
    flash_kernel<<<dim3(S_LEN / 64, N_HEADS), 128, FLASH_SMEM>>>(qkv, attn);

    // 4) out = attn @ W_proj     [2048,2048]
    sgemm128<<<dim3(HIDDEN / 128, S_LEN / 128), 256>>>(attn, W_proj, out, HIDDEN);
}

// round 3
// speedup vs baseline: 2.9586x; 2.9586x over previous
#include <cuda_runtime.h>
#include <cuda_bf16.h>
#include <cstdint>

typedef __nv_bfloat16 bf16;

#define S_LEN 2048
#define HID   2048
#define QKV_N 3072
#define NH    16
#define SCALE 0.08838834764831845f

// ---------------- scratch (static device allocations) ----------------
__device__ float g_qkv[S_LEN * QKV_N];
__device__ float g_S[(size_t)NH * S_LEN * S_LEN];        // 268 MB
__device__ bf16  g_Ph[(size_t)NH * S_LEN * S_LEN];       // 134 MB
__device__ bf16  g_Pl[(size_t)NH * S_LEN * S_LEN];       // 134 MB
__device__ float g_attn[S_LEN * HID];
__device__ bf16  g_xh[S_LEN * HID], g_xl[S_LEN * HID];
__device__ bf16  g_wh[QKV_N * HID], g_wl[QKV_N * HID];
__device__ bf16  g_qh[S_LEN * HID], g_ql[S_LEN * HID];
__device__ bf16  g_kh[S_LEN * 512], g_kl[S_LEN * 512];
__device__ bf16  g_vth[512 * S_LEN], g_vtl[512 * S_LEN];

// ---------------- helpers ----------------
__device__ __forceinline__ uint32_t smem_u32(const void* p) {
    uint32_t a;
    asm("{ .reg .u64 t; cvta.to.shared.u64 t, %1; cvt.u32.u64 %0, t; }" : "=r"(a) : "l"(p));
    return a;
}
#define CP16(dst, src) \
    asm volatile("cp.async.cg.shared.global [%0], [%1], 16;" :: "r"(dst), "l"(src))
#define CP_COMMIT() asm volatile("cp.async.commit_group;" ::: "memory")
#define CP_WAIT1()  asm volatile("cp.async.wait_group 1;" ::: "memory")
#define CP_WAIT0()  asm volatile("cp.async.wait_group 0;" ::: "memory")

__device__ __forceinline__ void ldsm_x4(uint32_t& r0, uint32_t& r1, uint32_t& r2,
                                        uint32_t& r3, uint32_t a) {
    asm volatile("ldmatrix.sync.aligned.m8n8.x4.shared.b16 {%0,%1,%2,%3}, [%4];"
                 : "=r"(r0), "=r"(r1), "=r"(r2), "=r"(r3) : "r"(a));
}
__device__ __forceinline__ void hmma(float* d, const uint32_t* a, const uint32_t* b) {
    asm volatile("mma.sync.aligned.m16n8k16.row.col.f32.bf16.bf16.f32 "
                 "{%0,%1,%2,%3}, {%4,%5,%6,%7}, {%8,%9}, {%0,%1,%2,%3};"
                 : "+f"(d[0]), "+f"(d[1]), "+f"(d[2]), "+f"(d[3])
                 : "r"(a[0]), "r"(a[1]), "r"(a[2]), "r"(a[3]), "r"(b[0]), "r"(b[1]));
}

// ---------------------------------------------------------------------------
// 3-term split-bf16 GEMM via mma.sync: C[M,N](fp32) = A @ B^T  (B is [N][K])
// 256 threads, BM=BN=128, BK=32, warp tile 32x64, double-buffered cp.async.
// Tile smem layout: 128 rows x 32 bf16, row stride 80 B (conflict-free ldmatrix).
// mode: 0 plain; 1 QK (causal block skip, B batch z/4); 2 PV (K limit, B batch z/4)
// ---------------------------------------------------------------------------
#define TROW   80
#define TILE_B (128 * TROW)            // 10240 B per tile
#define STAGE_B (4 * TILE_B)           // Ah, Al, Bh, Bl
#define GEMM_SMEM (2 * STAGE_B)        // 81920 B

__device__ __forceinline__ void tile_cp(const bf16* __restrict__ g, int ldg,
                                        int r0, int k0, uint32_t sdst, int t) {
#pragma unroll
    for (int u = 0; u < 2; u++) {
        int i = u * 256 + t;           // 0..511
        int row = i >> 2, c = i & 3;
        const bf16* src = g + (long long)(r0 + row) * ldg + k0 + c * 8;
        CP16(sdst + row * TROW + c * 16, src);
    }
}

__global__ __launch_bounds__(256) void gemm_bb3(
    const bf16* __restrict__ Ah, const bf16* __restrict__ Al, int lda, long long sA,
    const bf16* __restrict__ Bh, const bf16* __restrict__ Bl, int ldb, long long sB,
    float* __restrict__ C, int ldc, long long sC,
    int K, int mode)
{
    int rb = blockIdx.y, cb = blockIdx.x, z = blockIdx.z;
    if (mode == 1 && cb > rb) return;
    int k_end = (mode == 2) ? (rb + 1) * 128 : K;

    long long zb = (mode != 0) ? (long long)(z >> 2) * sB : (long long)z * sB;
    Ah += (long long)z * sA;  Al += (long long)z * sA;
    Bh += zb;                 Bl += zb;
    C  += (long long)z * sC;
    int row0 = rb * 128, col0 = cb * 128;

    extern __shared__ char sm[];
    uint32_t sbase = smem_u32(sm);
    int t = threadIdx.x, w = t >> 5, l = t & 31;
    int wm = w & 3, wn = w >> 2;       // warp tile: rows wm*32, cols wn*64

    float acc[2][8][4];
#pragma unroll
    for (int i = 0; i < 2; i++)
#pragma unroll
        for (int j = 0; j < 8; j++)
#pragma unroll
            for (int q = 0; q < 4; q++) acc[i][j][q] = 0.f;

    int niter = k_end / 32;
    uint32_t stg[2] = {sbase, sbase + STAGE_B};

    // prologue
    tile_cp(Ah, lda, row0, 0, stg[0],              t);
    tile_cp(Al, lda, row0, 0, stg[0] + TILE_B,     t);
    tile_cp(Bh, ldb, col0, 0, stg[0] + 2 * TILE_B, t);
    tile_cp(Bl, ldb, col0, 0, stg[0] + 3 * TILE_B, t);
    CP_COMMIT();

    // per-thread ldmatrix address components
    int a_row = wm * 32 + (l & 15);
    int a_kb  = ((l >> 4) & 1) * 16;
    int b_row = wn * 64 + (l & 7) + ((l >> 4) & 1) * 8;
    int b_kb  = ((l >> 3) & 1) * 16;

    for (int it = 0; it < niter; it++) {
        if (it + 1 < niter) {
            uint32_t nb = stg[(it + 1) & 1];
            int k0 = (it + 1) * 32;
            tile_cp(Ah, lda, row0, k0, nb,              t);
            tile_cp(Al, lda, row0, k0, nb + TILE_B,     t);
            tile_cp(Bh, ldb, col0, k0, nb + 2 * TILE_B, t);
            tile_cp(Bl, ldb, col0, k0, nb + 3 * TILE_B, t);
            CP_COMMIT();
            CP_WAIT1();
        } else {
            CP_WAIT0();
        }
        __syncthreads();

        uint32_t base = stg[it & 1];
#pragma unroll
        for (int ks = 0; ks < 2; ks++) {           // k = ks*16
            int kbyte = ks * 32;
            uint32_t ah[2][4], al[2][4], bh[8][2], bl[8][2];
#pragma unroll
            for (int mf = 0; mf < 2; mf++) {
                uint32_t aaddr = base + (a_row + mf * 16) * TROW + kbyte + a_kb;
                ldsm_x4(ah[mf][0], ah[mf][1], ah[mf][2], ah[mf][3], aaddr);
                ldsm_x4(al[mf][0], al[mf][1], al[mf][2], al[mf][3], aaddr + TILE_B);
            }
#pragma unroll
            for (int p = 0; p < 4; p++) {          // nfrag pair
                uint32_t baddr = base + 2 * TILE_B + (b_row + p * 16) * TROW + kbyte + b_kb;
                uint32_t r0, r1, r2, r3;
                ldsm_x4(r0, r1, r2, r3, baddr);
                bh[2 * p][0] = r0;     bh[2 * p][1] = r1;
                bh[2 * p + 1][0] = r2; bh[2 * p + 1][1] = r3;
                ldsm_x4(r0, r1, r2, r3, baddr + TILE_B);
                bl[2 * p][0] = r0;     bl[2 * p][1] = r1;
                bl[2 * p + 1][0] = r2; bl[2 * p + 1][1] = r3;
            }
#pragma unroll
            for (int mf = 0; mf < 2; mf++)
#pragma unroll
                for (int nf = 0; nf < 8; nf++) {
                    hmma(acc[mf][nf], ah[mf], bh[nf]);
                    hmma(acc[mf][nf], al[mf], bh[nf]);
                    hmma(acc[mf][nf], ah[mf], bl[nf]);
                }
        }
        __syncthreads();
    }

    // epilogue
#pragma unroll
    for (int mf = 0; mf < 2; mf++) {
        int r_lo = row0 + wm * 32 + mf * 16 + (l >> 2);
#pragma unroll
        for (int nf = 0; nf < 8; nf++) {
            int cix = col0 + wn * 64 + nf * 8 + (l & 3) * 2;
            float2 v0 = make_float2(acc[mf][nf][0], acc[mf][nf][1]);
            float2 v1 = make_float2(acc[mf][nf][2], acc[mf][nf][3]);
            *(float2*)&C[(long long)r_lo * ldc + cix]       = v0;
            *(float2*)&C[(long long)(r_lo + 8) * ldc + cix] = v1;
        }
    }
}

// ---------------------------------------------------------------------------
__global__ __launch_bounds__(256) void conv_k(const float* __restrict__ x,
                                              bf16* __restrict__ h, bf16* __restrict__ l, int n)
{
    int i = blockIdx.x * 256 + threadIdx.x;
    if (i >= n) return;
    float v = x[i];
    bf16 a = __float2bfloat16(v);
    h[i] = a;
    l[i] = __float2bfloat16(v - __bfloat162float(a));
}

__global__ __launch_bounds__(256) void transconv_k(const float* __restrict__ src, int sld,
                                                   int scol0, bf16* __restrict__ dh,
                                                   bf16* __restrict__ dl, int dld)
{
    __shared__ float tile[32][33];
    int tx = threadIdx.x, ty = threadIdx.y;
    int sr = blockIdx.x * 32;
    int sc = blockIdx.y * 32;
#pragma unroll
    for (int k = 0; k < 32; k += 8)
        tile[ty + k][tx] = src[(long long)(sr + ty + k) * sld + scol0 + sc + tx];
    __syncthreads();
#pragma unroll
    for (int k = 0; k < 32; k += 8) {
        float v = tile[tx][ty + k];
        bf16 h = __float2bfloat16(v);
        long long o = (long long)(sc + ty + k) * dld + sr + tx;
        dh[o] = h;
        dl[o] = __float2bfloat16(v - __bfloat162float(h));
    }
}

__global__ __launch_bounds__(256) void rope_split_k(const float* __restrict__ qkv,
    bf16* __restrict__ qh, bf16* __restrict__ ql,
    bf16* __restrict__ kh, bf16* __restrict__ kl)
{
    int idx = blockIdx.x * 256 + threadIdx.x;
    int i  = idx & 63;
    int hh = (idx >> 6) % 20;
    int s  = idx / (64 * 20);
    const float* p = qkv + (long long)s * QKV_N + ((hh < 16) ? hh * 128 : 2048 + (hh - 16) * 128);

    float f  = (float)s * __expf((float)i * -0.14391156831212787f);
    float sf = sinf(f), cf = cosf(f);
    float x1 = p[i], x2 = p[i + 64];
    float y1 = x1 * cosf(sf) - x2 * sinf(sf);
    float y2 = x2 * cosf(cf) + x1 * sinf(cf);

    if (hh < 16) {
        y1 *= SCALE; y2 *= SCALE;
        long long o = (long long)s * HID + hh * 128 + i;
        bf16 a = __float2bfloat16(y1);
        qh[o] = a; ql[o] = __float2bfloat16(y1 - __bfloat162float(a));
        bf16 b = __float2bfloat16(y2);
        qh[o + 64] = b; ql[o + 64] = __float2bfloat16(y2 - __bfloat162float(b));
    } else {
        long long o = (long long)s * 512 + (hh - 16) * 128 + i;
        bf16 a = __float2bfloat16(y1);
        kh[o] = a; kl[o] = __float2bfloat16(y1 - __bfloat162float(a));
        bf16 b = __float2bfloat16(y2);
        kh[o + 64] = b; kl[o + 64] = __float2bfloat16(y2 - __bfloat162float(b));
    }
}

__global__ __launch_bounds__(128) void softmax_k(const float* __restrict__ S,
                                                 bf16* __restrict__ Ph, bf16* __restrict__ Pl)
{
    __shared__ float r1[4], r2[4];
    long long row = blockIdx.x;                 // h*2048 + i
    int i = (int)(row & 2047);
    const float* s = S + row * S_LEN;
    bf16* ph = Ph + row * S_LEN;
    bf16* pl = Pl + row * S_LEN;
    int t = threadIdx.x;
    int wcols = ((i >> 7) + 1) << 7;

    float loc[16];
    int cnt = 0;
    float m = -1e30f;
    for (int j = t; j <= i; j += 128) { float v = s[j]; loc[cnt++] = v; m = fmaxf(m, v); }
#pragma unroll
    for (int o = 16; o; o >>= 1) m = fmaxf(m, __shfl_xor_sync(0xffffffffu, m, o));
    if ((t & 31) == 0) r1[t >> 5] = m;
    __syncthreads();
    float M = fmaxf(fmaxf(r1[0], r1[1]), fmaxf(r1[2], r1[3]));

    float sum = 0.f;
    for (int c = 0; c < cnt; c++) { float e = __expf(loc[c] - M); loc[c] = e; sum += e; }
#pragma unroll
    for (int o = 16; o; o >>= 1) sum += __shfl_xor_sync(0xffffffffu, sum, o);
    if ((t & 31) == 0) r2[t >> 5] = sum;
    __syncthreads();
    float inv = 1.f / (r2[0] + r2[1] + r2[2] + r2[3]);

    int c2 = 0;
    for (int j = t; j < wcols; j += 128) {
        float p = (j <= i) ? loc[c2++] * inv : 0.f;
        bf16 h = __float2bfloat16(p);
        ph[j] = h;
        pl[j] = __float2bfloat16(p - __bfloat162float(h));
    }
}

// ---------------------------------------------------------------------------
extern "C" void kernel_launch(void* const* d_in, const int* in_sizes, int n_in,
                              void* d_out, int out_size)
{
    const float* hidden = (const float*)d_in[0];
    const float* W_attn = (const float*)d_in[3];
    const float* W_proj = (const float*)d_in[4];
    float* out = (float*)d_out;

    float *qkv, *Smat, *attn;
    bf16 *xh, *xl, *wh, *wl, *qh, *ql, *kh, *kl, *vth, *vtl, *Ph, *Pl;
    cudaGetSymbolAddress((void**)&qkv, g_qkv);
    cudaGetSymbolAddress((void**)&Smat, g_S);
    cudaGetSymbolAddress((void**)&attn, g_attn);
    cudaGetSymbolAddress((void**)&xh, g_xh);   cudaGetSymbolAddress((void**)&xl, g_xl);
    cudaGetSymbolAddress((void**)&wh, g_wh);   cudaGetSymbolAddress((void**)&wl, g_wl);
    cudaGetSymbolAddress((void**)&qh, g_qh);   cudaGetSymbolAddress((void**)&ql, g_ql);
    cudaGetSymbolAddress((void**)&kh, g_kh);   cudaGetSymbolAddress((void**)&kl, g_kl);
    cudaGetSymbolAddress((void**)&vth, g_vth); cudaGetSymbolAddress((void**)&vtl, g_vtl);
    cudaGetSymbolAddress((void**)&Ph, g_Ph);   cudaGetSymbolAddress((void**)&Pl, g_Pl);

    cudaFuncSetAttribute(gemm_bb3, cudaFuncAttributeMaxDynamicSharedMemorySize, GEMM_SMEM);

    // 1) split inputs
    conv_k<<<(S_LEN * HID) / 256, 256>>>(hidden, xh, xl, S_LEN * HID);
    transconv_k<<<dim3(64, 96), dim3(32, 8)>>>(W_attn, QKV_N, 0, wh, wl, HID);

    // 2) qkv = hidden @ W_attn
    gemm_bb3<<<dim3(QKV_N / 128, S_LEN / 128, 1), 256, GEMM_SMEM>>>(
        xh, xl, HID, 0, wh, wl, HID, 0, qkv, QKV_N, 0, HID, 0);

    // 3) rope + split q/k ; transpose+split v
    rope_split_k<<<(S_LEN * 20 * 64) / 256, 256>>>(qkv, qh, ql, kh, kl);
    transconv_k<<<dim3(64, 16), dim3(32, 8)>>>(qkv, QKV_N, 2560, vth, vtl, S_LEN);

    // 4) S = (q*scale) @ k^T  per head (causal block skip)
    gemm_bb3<<<dim3(S_LEN / 128, S_LEN / 128, NH), 256, GEMM_SMEM>>>(
        qh, ql, HID, 128, kh, kl, 512, 128,
        Smat, S_LEN, (long long)S_LEN * S_LEN, 128, 1);

    // 5) masked softmax -> split P
    softmax_k<<<NH * S_LEN, 128>>>(Smat, Ph, Pl);

    // 6) attn = P @ V  per head (causal K limit)
    gemm_bb3<<<dim3(1, S_LEN / 128, NH), 256, GEMM_SMEM>>>(
        Ph, Pl, S_LEN, (long long)S_LEN * S_LEN, vth, vtl, S_LEN, (long long)128 * S_LEN,
        attn, HID, 128, S_LEN, 2);

    // 7) out = attn @ W_proj
    conv_k<<<(S_LEN * HID) / 256, 256>>>(attn, xh, xl, S_LEN * HID);
    transconv_k<<<dim3(64, 64), dim3(32, 8)>>>(W_proj, HID, 0, wh, wl, HID);
    gemm_bb3<<<dim3(HID / 128, S_LEN / 128, 1), 256, GEMM_SMEM>>>(
        xh, xl, HID, 0, wh, wl, HID, 0, out, HID, 0, HID, 0);
}

// round 4
// speedup vs baseline: 3.3276x; 1.1247x over previous
#include <cuda_runtime.h>
#include <cuda_bf16.h>
#include <cstdint>

typedef __nv_bfloat16 bf16;

#define S_LEN 2048
#define HID   2048
#define QKV_N 3072
#define NH    16
// q scale with log2(e) folded in (flash softmax runs in base-2)
#define QSCALE (0.08838834764831845f * 1.4426950408889634f)

// ---------------- scratch (static device allocations) ----------------
__device__ float g_qkv[S_LEN * QKV_N];
__device__ bf16  g_xh[S_LEN * HID], g_xl[S_LEN * HID];   // hidden split, then attn split
__device__ bf16  g_wh[QKV_N * HID], g_wl[QKV_N * HID];   // W^T split (attn, then proj)
__device__ bf16  g_qh[S_LEN * HID], g_ql[S_LEN * HID];
__device__ bf16  g_kh[S_LEN * 512], g_kl[S_LEN * 512];
__device__ bf16  g_vth[512 * S_LEN], g_vtl[512 * S_LEN]; // V^T per kv head

// ---------------- helpers ----------------
__device__ __forceinline__ uint32_t smem_u32(const void* p) {
    uint32_t a;
    asm("{ .reg .u64 t; cvta.to.shared.u64 t, %1; cvt.u32.u64 %0, t; }" : "=r"(a) : "l"(p));
    return a;
}
#define CP16(dst, src) \
    asm volatile("cp.async.cg.shared.global [%0], [%1], 16;" :: "r"(dst), "l"(src))
#define CP_COMMIT() asm volatile("cp.async.commit_group;" ::: "memory")
#define CP_WAIT1()  asm volatile("cp.async.wait_group 1;" ::: "memory")
#define CP_WAIT0()  asm volatile("cp.async.wait_group 0;" ::: "memory")

__device__ __forceinline__ void ldsm_x4(uint32_t& r0, uint32_t& r1, uint32_t& r2,
                                        uint32_t& r3, uint32_t a) {
    asm volatile("ldmatrix.sync.aligned.m8n8.x4.shared.b16 {%0,%1,%2,%3}, [%4];"
                 : "=r"(r0), "=r"(r1), "=r"(r2), "=r"(r3) : "r"(a));
}
__device__ __forceinline__ void hmma(float* d, const uint32_t* a, const uint32_t* b) {
    asm volatile("mma.sync.aligned.m16n8k16.row.col.f32.bf16.bf16.f32 "
                 "{%0,%1,%2,%3}, {%4,%5,%6,%7}, {%8,%9}, {%0,%1,%2,%3};"
                 : "+f"(d[0]), "+f"(d[1]), "+f"(d[2]), "+f"(d[3])
                 : "r"(a[0]), "r"(a[1]), "r"(a[2]), "r"(a[3]), "r"(b[0]), "r"(b[1]));
}
__device__ __forceinline__ float ex2(float x) {
    float r; asm("ex2.approx.f32 %0, %1;" : "=f"(r) : "f"(x)); return r;
}
// pack two fp32 -> bf16x2 (lo element = e_lo, hi element = e_hi), round-nearest
__device__ __forceinline__ uint32_t pack_bf16(float e_lo, float e_hi) {
    uint32_t r;
    asm("cvt.rn.bf16x2.f32 %0, %1, %2;" : "=r"(r) : "f"(e_hi), "f"(e_lo));
    return r;
}
// pack upper halves of two fp32 bit patterns: {a.hi16 (low), b.hi16 (high)}
__device__ __forceinline__ uint32_t prmt_hi(uint32_t a, uint32_t b) {
    uint32_t r; asm("prmt.b32 %0, %1, %2, 0x7632;" : "=r"(r) : "r"(a), "r"(b)); return r;
}
__device__ __forceinline__ float trunc_bf(float x) {
    return __uint_as_float(__float_as_uint(x) & 0xFFFF0000u);
}

// ---------------------------------------------------------------------------
// 3-term split-bf16 GEMM via mma.sync (projections): C = A @ B^T, B is [N][K]
// ---------------------------------------------------------------------------
#define TROW   80
#define TILE_B (128 * TROW)
#define STAGE_B (4 * TILE_B)
#define GEMM_SMEM (2 * STAGE_B)

__device__ __forceinline__ void tile_cp(const bf16* __restrict__ g, int ldg,
                                        int r0, int k0, uint32_t sdst, int t) {
#pragma unroll
    for (int u = 0; u < 2; u++) {
        int i = u * 256 + t;
        int row = i >> 2, c = i & 3;
        const bf16* src = g + (long long)(r0 + row) * ldg + k0 + c * 8;
        CP16(sdst + row * TROW + c * 16, src);
    }
}

__global__ __launch_bounds__(256) void gemm_bb3(
    const bf16* __restrict__ Ah, const bf16* __restrict__ Al, int lda,
    const bf16* __restrict__ Bh, const bf16* __restrict__ Bl, int ldb,
    float* __restrict__ C, int ldc, int K)
{
    int rb = blockIdx.y, cb = blockIdx.x;
    int row0 = rb * 128, col0 = cb * 128;

    extern __shared__ char sm[];
    uint32_t sbase = smem_u32(sm);
    int t = threadIdx.x, w = t >> 5, l = t & 31;
    int wm = w & 3, wn = w >> 2;

    float acc[2][8][4];
#pragma unroll
    for (int i = 0; i < 2; i++)
#pragma unroll
        for (int j = 0; j < 8; j++)
#pragma unroll
            for (int q = 0; q < 4; q++) acc[i][j][q] = 0.f;

    int niter = K / 32;
    uint32_t stg[2] = {sbase, sbase + STAGE_B};

    tile_cp(Ah, lda, row0, 0, stg[0],              t);
    tile_cp(Al, lda, row0, 0, stg[0] + TILE_B,     t);
    tile_cp(Bh, ldb, col0, 0, stg[0] + 2 * TILE_B, t);
    tile_cp(Bl, ldb, col0, 0, stg[0] + 3 * TILE_B, t);
    CP_COMMIT();

    int a_row = wm * 32 + (l & 15);
    int a_kb  = ((l >> 4) & 1) * 16;
    int b_row = wn * 64 + (l & 7) + ((l >> 4) & 1) * 8;
    int b_kb  = ((l >> 3) & 1) * 16;

    for (int it = 0; it < niter; it++) {
        if (it + 1 < niter) {
            uint32_t nb = stg[(it + 1) & 1];
            int k0 = (it + 1) * 32;
            tile_cp(Ah, lda, row0, k0, nb,              t);
            tile_cp(Al, lda, row0, k0, nb + TILE_B,     t);
            tile_cp(Bh, ldb, col0, k0, nb + 2 * TILE_B, t);
            tile_cp(Bl, ldb, col0, k0, nb + 3 * TILE_B, t);
            CP_COMMIT();
            CP_WAIT1();
        } else {
            CP_WAIT0();
        }
        __syncthreads();

        uint32_t base = stg[it & 1];
#pragma unroll
        for (int ks = 0; ks < 2; ks++) {
            int kbyte = ks * 32;
            uint32_t ah[2][4], al[2][4], bh[8][2], bl[8][2];
#pragma unroll
            for (int mf = 0; mf < 2; mf++) {
                uint32_t aaddr = base + (a_row + mf * 16) * TROW + kbyte + a_kb;
                ldsm_x4(ah[mf][0], ah[mf][1], ah[mf][2], ah[mf][3], aaddr);
                ldsm_x4(al[mf][0], al[mf][1], al[mf][2], al[mf][3], aaddr + TILE_B);
            }
#pragma unroll
            for (int p = 0; p < 4; p++) {
                uint32_t baddr = base + 2 * TILE_B + (b_row + p * 16) * TROW + kbyte + b_kb;
                uint32_t r0, r1, r2, r3;
                ldsm_x4(r0, r1, r2, r3, baddr);
                bh[2 * p][0] = r0;     bh[2 * p][1] = r1;
                bh[2 * p + 1][0] = r2; bh[2 * p + 1][1] = r3;
                ldsm_x4(r0, r1, r2, r3, baddr + TILE_B);
                bl[2 * p][0] = r0;     bl[2 * p][1] = r1;
                bl[2 * p + 1][0] = r2; bl[2 * p + 1][1] = r3;
            }
#pragma unroll
            for (int mf = 0; mf < 2; mf++)
#pragma unroll
                for (int nf = 0; nf < 8; nf++) {
                    hmma(acc[mf][nf], ah[mf], bh[nf]);
                    hmma(acc[mf][nf], al[mf], bh[nf]);
                    hmma(acc[mf][nf], ah[mf], bl[nf]);
                }
        }
        __syncthreads();
    }

#pragma unroll
    for (int mf = 0; mf < 2; mf++) {
        int r_lo = row0 + wm * 32 + mf * 16 + (l >> 2);
#pragma unroll
        for (int nf = 0; nf < 8; nf++) {
            int cix = col0 + wn * 64 + nf * 8 + (l & 3) * 2;
            *(float2*)&C[(long long)r_lo * ldc + cix] =
                make_float2(acc[mf][nf][0], acc[mf][nf][1]);
            *(float2*)&C[(long long)(r_lo + 8) * ldc + cix] =
                make_float2(acc[mf][nf][2], acc[mf][nf][3]);
        }
    }
}

// ---------------------------------------------------------------------------
// Fused flash attention via mma.sync. One CTA = (head, 128-row q block).
// 8 warps x 16 q-rows, KV blocks of 64, hi/lo double-buffered cp.async.
// Output written as split bf16 (hi/lo) directly for the proj GEMM.
// ---------------------------------------------------------------------------
#define FL_QROW 272                    // 128 bf16 + 16 B pad
#define FL_VROW 144                    // 64 bf16 + 16 B pad
#define FL_QT (128 * FL_QROW)          // 34816
#define FL_KT (64  * FL_QROW)          // 17408
#define FL_VT (128 * FL_VROW)          // 18432
#define FL_STG (2 * FL_KT + 2 * FL_VT) // 71680
#define FL_SMEM (2 * FL_QT + 2 * FL_STG) // 212992

__device__ __forceinline__ void cp_rows(const bf16* __restrict__ g, int ldg,
                                        int row0, int col0, uint32_t sdst,
                                        int stride, int cps_per_row, int nops, int t) {
    for (int o = t; o < nops; o += 256) {
        int r = o / cps_per_row, c = o % cps_per_row;
        CP16(sdst + r * stride + c * 16,
             g + (long long)(row0 + r) * ldg + col0 + c * 8);
    }
}

__global__ __launch_bounds__(256) void flash_k(
    const bf16* __restrict__ qh, const bf16* __restrict__ ql,
    const bf16* __restrict__ kh, const bf16* __restrict__ kl,
    const bf16* __restrict__ vth, const bf16* __restrict__ vtl,
    bf16* __restrict__ oh, bf16* __restrict__ ol)
{
    int id = blockIdx.x;
    int qb = id & 15, h = id >> 4;
    int kvh = h >> 2;
    int q0 = qb * 128;

    extern __shared__ char sm[];
    uint32_t S = smem_u32(sm);
    uint32_t smQ = S;                          // Qh, Ql contiguous (Ql = +FL_QT)
    int t = threadIdx.x, w = t >> 5, l = t & 31;
    int g = l >> 2, tg = l & 3;

    // prologue: Q hi/lo + stage0 KV in one group
    cp_rows(qh, HID, q0, h * 128, smQ,         FL_QROW, 16, 2048, t);
    cp_rows(ql, HID, q0, h * 128, smQ + FL_QT, FL_QROW, 16, 2048, t);
    {
        uint32_t st = S + 2 * FL_QT;
        cp_rows(kh, 512, 0, kvh * 128, st,                      FL_QROW, 16, 1024, t);
        cp_rows(kl, 512, 0, kvh * 128, st + FL_KT,              FL_QROW, 16, 1024, t);
        cp_rows(vth, S_LEN, kvh * 128, 0, st + 2 * FL_KT,         FL_VROW, 8, 1024, t);
        cp_rows(vtl, S_LEN, kvh * 128, 0, st + 2 * FL_KT + FL_VT, FL_VROW, 8, 1024, t);
    }
    CP_COMMIT();

    float acc[16][4];
#pragma unroll
    for (int nf = 0; nf < 16; nf++)
#pragma unroll
        for (int c = 0; c < 4; c++) acc[nf][c] = 0.f;
    float m0 = -1e30f, m1 = -1e30f, l0 = 0.f, l1 = 0.f;

    int niter = 2 * qb + 2;

    int a_row = w * 16 + (l & 15);
    int a_kb  = ((l >> 4) & 1) * 16;
    int b_sub = (l & 7) + ((l >> 4) & 1) * 8;
    int b_kb  = ((l >> 3) & 1) * 16;

    for (int jj = 0; jj < niter; jj++) {
        if (jj + 1 < niter) {
            uint32_t st = S + 2 * FL_QT + ((jj + 1) & 1) * FL_STG;
            int k0 = (jj + 1) * 64;
            cp_rows(kh, 512, k0, kvh * 128, st,                      FL_QROW, 16, 1024, t);
            cp_rows(kl, 512, k0, kvh * 128, st + FL_KT,              FL_QROW, 16, 1024, t);
            cp_rows(vth, S_LEN, kvh * 128, k0, st + 2 * FL_KT,         FL_VROW, 8, 1024, t);
            cp_rows(vtl, S_LEN, kvh * 128, k0, st + 2 * FL_KT + FL_VT, FL_VROW, 8, 1024, t);
            CP_COMMIT();
            CP_WAIT1();
        } else {
            CP_WAIT0();
        }
        __syncthreads();

        // warps 0-3 (rows q0..q0+63) are fully masked in the last diag block
        bool active = !(jj == 2 * qb + 1 && w < 4);
        if (active) {
            uint32_t base = S + 2 * FL_QT + (jj & 1) * FL_STG;
            uint32_t bKh = base, bVh = base + 2 * FL_KT;

            float sf[8][4];
#pragma unroll
            for (int nf = 0; nf < 8; nf++)
#pragma unroll
                for (int c = 0; c < 4; c++) sf[nf][c] = 0.f;

            // ---- S = Q K^T (3-term split) ----
#pragma unroll
            for (int ks = 0; ks < 8; ks++) {
                uint32_t aaddr = smQ + a_row * FL_QROW + ks * 32 + a_kb;
                uint32_t ah[4], al[4];
                ldsm_x4(ah[0], ah[1], ah[2], ah[3], aaddr);
                ldsm_x4(al[0], al[1], al[2], al[3], aaddr + FL_QT);
#pragma unroll
                for (int p = 0; p < 4; p++) {
                    uint32_t baddr = bKh + (p * 16 + b_sub) * FL_QROW + ks * 32 + b_kb;
                    uint32_t r0, r1, r2, r3, s0, s1, s2, s3;
                    ldsm_x4(r0, r1, r2, r3, baddr);
                    ldsm_x4(s0, s1, s2, s3, baddr + FL_KT);
                    uint32_t bh0[2] = {r0, r1}, bh1[2] = {r2, r3};
                    uint32_t bl0[2] = {s0, s1}, bl1[2] = {s2, s3};
                    hmma(sf[2 * p],     ah, bh0);
                    hmma(sf[2 * p + 1], ah, bh1);
                    hmma(sf[2 * p],     al, bh0);
                    hmma(sf[2 * p + 1], al, bh1);
                    hmma(sf[2 * p],     ah, bl0);
                    hmma(sf[2 * p + 1], ah, bl1);
                }
            }

            // ---- causal mask (diag blocks only) ----
            if (jj >= 2 * qb) {
                int r0g = q0 + w * 16 + g;
#pragma unroll
                for (int nf = 0; nf < 8; nf++) {
                    int cg = jj * 64 + nf * 8 + 2 * tg;
                    if (cg     > r0g)     sf[nf][0] = -1e30f;
                    if (cg + 1 > r0g)     sf[nf][1] = -1e30f;
                    if (cg     > r0g + 8) sf[nf][2] = -1e30f;
                    if (cg + 1 > r0g + 8) sf[nf][3] = -1e30f;
                }
            }

            // ---- online softmax (base-2; scale pre-folded into q) ----
            float mx0 = m0, mx1 = m1;
#pragma unroll
            for (int nf = 0; nf < 8; nf++) {
                mx0 = fmaxf(mx0, fmaxf(sf[nf][0], sf[nf][1]));
                mx1 = fmaxf(mx1, fmaxf(sf[nf][2], sf[nf][3]));
            }
            mx0 = fmaxf(mx0, __shfl_xor_sync(0xffffffffu, mx0, 1));
            mx0 = fmaxf(mx0, __shfl_xor_sync(0xffffffffu, mx0, 2));
            mx1 = fmaxf(mx1, __shfl_xor_sync(0xffffffffu, mx1, 1));
            mx1 = fmaxf(mx1, __shfl_xor_sync(0xffffffffu, mx1, 2));
            float al0 = ex2(m0 - mx0), al1 = ex2(m1 - mx1);
            m0 = mx0; m1 = mx1;
            l0 *= al0; l1 *= al1;
#pragma unroll
            for (int nf = 0; nf < 8; nf++) {
                float p0 = ex2(sf[nf][0] - m0);
                float p1 = ex2(sf[nf][1] - m0);
                float p2 = ex2(sf[nf][2] - m1);
                float p3 = ex2(sf[nf][3] - m1);
                sf[nf][0] = p0; sf[nf][1] = p1; sf[nf][2] = p2; sf[nf][3] = p3;
                l0 += p0 + p1; l1 += p2 + p3;
            }
#pragma unroll
            for (int nf = 0; nf < 16; nf++) {
                acc[nf][0] *= al0; acc[nf][1] *= al0;
                acc[nf][2] *= al1; acc[nf][3] *= al1;
            }

            // ---- PV: acc += P V (3-term split), P packed in registers ----
#pragma unroll
            for (int u = 0; u < 4; u++) {
                uint32_t ph[4], pl[4];
                {
                    float e00 = sf[2 * u][0],     e01 = sf[2 * u][1];
                    float e10 = sf[2 * u][2],     e11 = sf[2 * u][3];
                    float e20 = sf[2 * u + 1][0], e21 = sf[2 * u + 1][1];
                    float e30 = sf[2 * u + 1][2], e31 = sf[2 * u + 1][3];
                    ph[0] = prmt_hi(__float_as_uint(e00), __float_as_uint(e01));
                    ph[1] = prmt_hi(__float_as_uint(e10), __float_as_uint(e11));
                    ph[2] = prmt_hi(__float_as_uint(e20), __float_as_uint(e21));
                    ph[3] = prmt_hi(__float_as_uint(e30), __float_as_uint(e31));
                    pl[0] = pack_bf16(e00 - trunc_bf(e00), e01 - trunc_bf(e01));
                    pl[1] = pack_bf16(e10 - trunc_bf(e10), e11 - trunc_bf(e11));
                    pl[2] = pack_bf16(e20 - trunc_bf(e20), e21 - trunc_bf(e21));
                    pl[3] = pack_bf16(e30 - trunc_bf(e30), e31 - trunc_bf(e31));
                }
#pragma unroll
                for (int p = 0; p < 8; p++) {
                    uint32_t vaddr = bVh + (p * 16 + b_sub) * FL_VROW + u * 32 + b_kb;
                    uint32_t r0, r1, r2, r3, s0, s1, s2, s3;
                    ldsm_x4(r0, r1, r2, r3, vaddr);
                    ldsm_x4(s0, s1, s2, s3, vaddr + FL_VT);
                    uint32_t vh0[2] = {r0, r1}, vh1[2] = {r2, r3};
                    uint32_t vl0[2] = {s0, s1}, vl1[2] = {s2, s3};
                    hmma(acc[2 * p],     ph, vh0);
                    hmma(acc[2 * p + 1], ph, vh1);
                    hmma(acc[2 * p],     pl, vh0);
                    hmma(acc[2 * p + 1], pl, vh1);
                    hmma(acc[2 * p],     ph, vl0);
                    hmma(acc[2 * p + 1], ph, vl1);
                }
            }
        }
        __syncthreads();
    }

    // ---- normalize + write split-bf16 output ----
    l0 += __shfl_xor_sync(0xffffffffu, l0, 1);
    l0 += __shfl_xor_sync(0xffffffffu, l0, 2);
    l1 += __shfl_xor_sync(0xffffffffu, l1, 1);
    l1 += __shfl_xor_sync(0xffffffffu, l1, 2);
    float i0 = 1.f / l0, i1 = 1.f / l1;
    int row0 = q0 + w * 16 + g;
#pragma unroll
    for (int nf = 0; nf < 16; nf++) {
        int col = h * 128 + nf * 8 + 2 * tg;
        float o0 = acc[nf][0] * i0, o1 = acc[nf][1] * i0;
        float o2 = acc[nf][2] * i1, o3 = acc[nf][3] * i1;
        uint32_t hw0 = pack_bf16(o0, o1);
        uint32_t hw1 = pack_bf16(o2, o3);
        float h00 = __uint_as_float(hw0 << 16), h01 = __uint_as_float(hw0 & 0xFFFF0000u);
        float h10 = __uint_as_float(hw1 << 16), h11 = __uint_as_float(hw1 & 0xFFFF0000u);
        uint32_t lw0 = pack_bf16(o0 - h00, o1 - h01);
        uint32_t lw1 = pack_bf16(o2 - h10, o3 - h11);
        *(uint32_t*)&oh[(long long)row0 * HID + col]       = hw0;
        *(uint32_t*)&ol[(long long)row0 * HID + col]       = lw0;
        *(uint32_t*)&oh[(long long)(row0 + 8) * HID + col] = hw1;
        *(uint32_t*)&ol[(long long)(row0 + 8) * HID + col] = lw1;
    }
}

// ---------------------------------------------------------------------------
__global__ __launch_bounds__(256) void conv_k(const float* __restrict__ x,
                                              bf16* __restrict__ h, bf16* __restrict__ l, int n)
{
    int i = blockIdx.x * 256 + threadIdx.x;
    if (i >= n) return;
    float v = x[i];
    bf16 a = __float2bfloat16(v);
    h[i] = a;
    l[i] = __float2bfloat16(v - __bfloat162float(a));
}

__global__ __launch_bounds__(256) void transconv_k(const float* __restrict__ src, int sld,
                                                   int scol0, bf16* __restrict__ dh,
                                                   bf16* __restrict__ dl, int dld)
{
    __shared__ float tile[32][33];
    int tx = threadIdx.x, ty = threadIdx.y;
    int sr = blockIdx.x * 32;
    int sc = blockIdx.y * 32;
#pragma unroll
    for (int k = 0; k < 32; k += 8)
        tile[ty + k][tx] = src[(long long)(sr + ty + k) * sld + scol0 + sc + tx];
    __syncthreads();
#pragma unroll
    for (int k = 0; k < 32; k += 8) {
        float v = tile[tx][ty + k];
        bf16 h = __float2bfloat16(v);
        long long o = (long long)(sc + ty + k) * dld + sr + tx;
        dh[o] = h;
        dl[o] = __float2bfloat16(v - __bfloat162float(h));
    }
}

__global__ __launch_bounds__(256) void rope_split_k(const float* __restrict__ qkv,
    bf16* __restrict__ qh, bf16* __restrict__ ql,
    bf16* __restrict__ kh, bf16* __restrict__ kl)
{
    int idx = blockIdx.x * 256 + threadIdx.x;
    int i  = idx & 63;
    int hh = (idx >> 6) % 20;
    int s  = idx / (64 * 20);
    const float* p = qkv + (long long)s * QKV_N + ((hh < 16) ? hh * 128 : 2048 + (hh - 16) * 128);

    float f  = (float)s * __expf((float)i * -0.14391156831212787f);
    float sf = sinf(f), cf = cosf(f);
    float x1 = p[i], x2 = p[i + 64];
    float y1 = x1 * cosf(sf) - x2 * sinf(sf);
    float y2 = x2 * cosf(cf) + x1 * sinf(cf);

    if (hh < 16) {
        y1 *= QSCALE; y2 *= QSCALE;     // softmax scale * log2(e) folded in
        long long o = (long long)s * HID + hh * 128 + i;
        bf16 a = __float2bfloat16(y1);
        qh[o] = a; ql[o] = __float2bfloat16(y1 - __bfloat162float(a));
        bf16 b = __float2bfloat16(y2);
        qh[o + 64] = b; ql[o + 64] = __float2bfloat16(y2 - __bfloat162float(b));
    } else {
        long long o = (long long)s * 512 + (hh - 16) * 128 + i;
        bf16 a = __float2bfloat16(y1);
        kh[o] = a; kl[o] = __float2bfloat16(y1 - __bfloat162float(a));
        bf16 b = __float2bfloat16(y2);
        kh[o + 64] = b; kl[o + 64] = __float2bfloat16(y2 - __bfloat162float(b));
    }
}

// ---------------------------------------------------------------------------
extern "C" void kernel_launch(void* const* d_in, const int* in_sizes, int n_in,
                              void* d_out, int out_size)
{
    const float* hidden = (const float*)d_in[0];
    const float* W_attn = (const float*)d_in[3];
    const float* W_proj = (const float*)d_in[4];
    float* out = (float*)d_out;

    float* qkv;
    bf16 *xh, *xl, *wh, *wl, *qh, *ql, *kh, *kl, *vth, *vtl;
    cudaGetSymbolAddress((void**)&qkv, g_qkv);
    cudaGetSymbolAddress((void**)&xh, g_xh);   cudaGetSymbolAddress((void**)&xl, g_xl);
    cudaGetSymbolAddress((void**)&wh, g_wh);   cudaGetSymbolAddress((void**)&wl, g_wl);
    cudaGetSymbolAddress((void**)&qh, g_qh);   cudaGetSymbolAddress((void**)&ql, g_ql);
    cudaGetSymbolAddress((void**)&kh, g_kh);   cudaGetSymbolAddress((void**)&kl, g_kl);
    cudaGetSymbolAddress((void**)&vth, g_vth); cudaGetSymbolAddress((void**)&vtl, g_vtl);

    cudaFuncSetAttribute(gemm_bb3, cudaFuncAttributeMaxDynamicSharedMemorySize, GEMM_SMEM);
    cudaFuncSetAttribute(flash_k, cudaFuncAttributeMaxDynamicSharedMemorySize, FL_SMEM);

    // 1) split inputs
    conv_k<<<(S_LEN * HID) / 256, 256>>>(hidden, xh, xl, S_LEN * HID);
    transconv_k<<<dim3(64, 96), dim3(32, 8)>>>(W_attn, QKV_N, 0, wh, wl, HID);

    // 2) qkv = hidden @ W_attn
    gemm_bb3<<<dim3(QKV_N / 128, S_LEN / 128), 256, GEMM_SMEM>>>(
        xh, xl, HID, wh, wl, HID, qkv, QKV_N, HID);

    // 3) rope + split q/k ; transpose+split v
    rope_split_k<<<(S_LEN * 20 * 64) / 256, 256>>>(qkv, qh, ql, kh, kl);
    transconv_k<<<dim3(64, 16), dim3(32, 8)>>>(qkv, QKV_N, 2560, vth, vtl, S_LEN);

    // 4) fused flash attention -> split bf16 attn (xh, xl)
    flash_k<<<256, 256, FL_SMEM>>>(qh, ql, kh, kl, vth, vtl, xh, xl);

    // 5) out = attn @ W_proj
    transconv_k<<<dim3(64, 64), dim3(32, 8)>>>(W_proj, HID, 0, wh, wl, HID);
    gemm_bb3<<<dim3(HID / 128, S_LEN / 128), 256, GEMM_SMEM>>>(
        xh, xl, HID, wh, wl, HID, out, HID, HID);
}

// round 5
// speedup vs baseline: 3.8529x; 1.1578x over previous
#include <cuda_runtime.h>
#include <cuda_bf16.h>
#include <cstdint>

typedef __nv_bfloat16 bf16;

#define S_LEN 2048
#define HID   2048
#define QKV_N 3072
#define NH    16
// q scale with log2(e) folded in (flash softmax runs in base-2)
#define QSCALE (0.08838834764831845f * 1.4426950408889634f)

// ---------------- scratch (static device allocations) ----------------
__device__ float g_qkv[S_LEN * QKV_N];
__device__ bf16  g_xh[S_LEN * HID], g_xl[S_LEN * HID];   // hidden split, then attn split
__device__ bf16  g_wh[QKV_N * HID], g_wl[QKV_N * HID];   // W_attn^T split
__device__ bf16  g_w2h[HID * HID],  g_w2l[HID * HID];    // W_proj^T split
__device__ bf16  g_qh[S_LEN * HID], g_ql[S_LEN * HID];
__device__ bf16  g_kh[S_LEN * 512], g_kl[S_LEN * 512];
__device__ bf16  g_vth[512 * S_LEN], g_vtl[512 * S_LEN]; // V^T per kv head

// ---------------- helpers ----------------
__device__ __forceinline__ uint32_t smem_u32(const void* p) {
    uint32_t a;
    asm("{ .reg .u64 t; cvta.to.shared.u64 t, %1; cvt.u32.u64 %0, t; }" : "=r"(a) : "l"(p));
    return a;
}
#define CP16(dst, src) \
    asm volatile("cp.async.cg.shared.global [%0], [%1], 16;" :: "r"(dst), "l"(src))
#define CP_COMMIT() asm volatile("cp.async.commit_group;" ::: "memory")
#define CP_WAIT1()  asm volatile("cp.async.wait_group 1;" ::: "memory")
#define CP_WAIT0()  asm volatile("cp.async.wait_group 0;" ::: "memory")

__device__ __forceinline__ void ldsm_x4(uint32_t& r0, uint32_t& r1, uint32_t& r2,
                                        uint32_t& r3, uint32_t a) {
    asm volatile("ldmatrix.sync.aligned.m8n8.x4.shared.b16 {%0,%1,%2,%3}, [%4];"
                 : "=r"(r0), "=r"(r1), "=r"(r2), "=r"(r3) : "r"(a));
}
__device__ __forceinline__ void hmma(float* d, const uint32_t* a, const uint32_t* b) {
    asm volatile("mma.sync.aligned.m16n8k16.row.col.f32.bf16.bf16.f32 "
                 "{%0,%1,%2,%3}, {%4,%5,%6,%7}, {%8,%9}, {%0,%1,%2,%3};"
                 : "+f"(d[0]), "+f"(d[1]), "+f"(d[2]), "+f"(d[3])
                 : "r"(a[0]), "r"(a[1]), "r"(a[2]), "r"(a[3]), "r"(b[0]), "r"(b[1]));
}
__device__ __forceinline__ float ex2(float x) {
    float r; asm("ex2.approx.f32 %0, %1;" : "=f"(r) : "f"(x)); return r;
}
__device__ __forceinline__ uint32_t pack_bf16(float e_lo, float e_hi) {
    uint32_t r;
    asm("cvt.rn.bf16x2.f32 %0, %1, %2;" : "=r"(r) : "f"(e_hi), "f"(e_lo));
    return r;
}
__device__ __forceinline__ uint32_t prmt_hi(uint32_t a, uint32_t b) {
    uint32_t r; asm("prmt.b32 %0, %1, %2, 0x7632;" : "=r"(r) : "r"(a), "r"(b)); return r;
}
__device__ __forceinline__ float trunc_bf(float x) {
    return __uint_as_float(__float_as_uint(x) & 0xFFFF0000u);
}

// ---------------------------------------------------------------------------
// 3-term split-bf16 GEMM via mma.sync (projections): C = A @ B^T, B is [N][K]
// ---------------------------------------------------------------------------
#define TROW   80
#define TILE_B (128 * TROW)
#define STAGE_B (4 * TILE_B)
#define GEMM_SMEM (2 * STAGE_B)

__device__ __forceinline__ void tile_cp(const bf16* __restrict__ g, int ldg,
                                        int r0, int k0, uint32_t sdst, int t) {
#pragma unroll
    for (int u = 0; u < 2; u++) {
        int i = u * 256 + t;
        int row = i >> 2, c = i & 3;
        const bf16* src = g + (long long)(r0 + row) * ldg + k0 + c * 8;
        CP16(sdst + row * TROW + c * 16, src);
    }
}

__global__ __launch_bounds__(256) void gemm_bb3(
    const bf16* __restrict__ Ah, const bf16* __restrict__ Al, int lda,
    const bf16* __restrict__ Bh, const bf16* __restrict__ Bl, int ldb,
    float* __restrict__ C, int ldc, int K)
{
    int rb = blockIdx.y, cb = blockIdx.x;
    int row0 = rb * 128, col0 = cb * 128;

    extern __shared__ char sm[];
    uint32_t sbase = smem_u32(sm);
    int t = threadIdx.x, w = t >> 5, l = t & 31;
    int wm = w & 3, wn = w >> 2;

    float acc[2][8][4];
#pragma unroll
    for (int i = 0; i < 2; i++)
#pragma unroll
        for (int j = 0; j < 8; j++)
#pragma unroll
            for (int q = 0; q < 4; q++) acc[i][j][q] = 0.f;

    int niter = K / 32;
    uint32_t stg[2] = {sbase, sbase + STAGE_B};

    tile_cp(Ah, lda, row0, 0, stg[0],              t);
    tile_cp(Al, lda, row0, 0, stg[0] + TILE_B,     t);
    tile_cp(Bh, ldb, col0, 0, stg[0] + 2 * TILE_B, t);
    tile_cp(Bl, ldb, col0, 0, stg[0] + 3 * TILE_B, t);
    CP_COMMIT();

    int a_row = wm * 32 + (l & 15);
    int a_kb  = ((l >> 4) & 1) * 16;
    int b_row = wn * 64 + (l & 7) + ((l >> 4) & 1) * 8;
    int b_kb  = ((l >> 3) & 1) * 16;

    for (int it = 0; it < niter; it++) {
        if (it + 1 < niter) {
            uint32_t nb = stg[(it + 1) & 1];
            int k0 = (it + 1) * 32;
            tile_cp(Ah, lda, row0, k0, nb,              t);
            tile_cp(Al, lda, row0, k0, nb + TILE_B,     t);
            tile_cp(Bh, ldb, col0, k0, nb + 2 * TILE_B, t);
            tile_cp(Bl, ldb, col0, k0, nb + 3 * TILE_B, t);
            CP_COMMIT();
            CP_WAIT1();
        } else {
            CP_WAIT0();
        }
        __syncthreads();

        uint32_t base = stg[it & 1];
#pragma unroll
        for (int ks = 0; ks < 2; ks++) {
            int kbyte = ks * 32;
            uint32_t ah[2][4], al[2][4], bh[8][2], bl[8][2];
#pragma unroll
            for (int mf = 0; mf < 2; mf++) {
                uint32_t aaddr = base + (a_row + mf * 16) * TROW + kbyte + a_kb;
                ldsm_x4(ah[mf][0], ah[mf][1], ah[mf][2], ah[mf][3], aaddr);
                ldsm_x4(al[mf][0], al[mf][1], al[mf][2], al[mf][3], aaddr + TILE_B);
            }
#pragma unroll
            for (int p = 0; p < 4; p++) {
                uint32_t baddr = base + 2 * TILE_B + (b_row + p * 16) * TROW + kbyte + b_kb;
                uint32_t r0, r1, r2, r3;
                ldsm_x4(r0, r1, r2, r3, baddr);
                bh[2 * p][0] = r0;     bh[2 * p][1] = r1;
                bh[2 * p + 1][0] = r2; bh[2 * p + 1][1] = r3;
                ldsm_x4(r0, r1, r2, r3, baddr + TILE_B);
                bl[2 * p][0] = r0;     bl[2 * p][1] = r1;
                bl[2 * p + 1][0] = r2; bl[2 * p + 1][1] = r3;
            }
            // term-outer: 16 independent MMAs per sweep (no same-acc chains)
#pragma unroll
            for (int mf = 0; mf < 2; mf++)
#pragma unroll
                for (int nf = 0; nf < 8; nf++) hmma(acc[mf][nf], ah[mf], bh[nf]);
#pragma unroll
            for (int mf = 0; mf < 2; mf++)
#pragma unroll
                for (int nf = 0; nf < 8; nf++) hmma(acc[mf][nf], al[mf], bh[nf]);
#pragma unroll
            for (int mf = 0; mf < 2; mf++)
#pragma unroll
                for (int nf = 0; nf < 8; nf++) hmma(acc[mf][nf], ah[mf], bl[nf]);
        }
        __syncthreads();
    }

#pragma unroll
    for (int mf = 0; mf < 2; mf++) {
        int r_lo = row0 + wm * 32 + mf * 16 + (l >> 2);
#pragma unroll
        for (int nf = 0; nf < 8; nf++) {
            int cix = col0 + wn * 64 + nf * 8 + (l & 3) * 2;
            *(float2*)&C[(long long)r_lo * ldc + cix] =
                make_float2(acc[mf][nf][0], acc[mf][nf][1]);
            *(float2*)&C[(long long)(r_lo + 8) * ldc + cix] =
                make_float2(acc[mf][nf][2], acc[mf][nf][3]);
        }
    }
}

// ---------------------------------------------------------------------------
// Fused flash attention via mma.sync. One CTA = (head, 128-row q block).
// Heavy-first CTA mapping for load balance.
// ---------------------------------------------------------------------------
#define FL_QROW 272
#define FL_VROW 144
#define FL_QT (128 * FL_QROW)
#define FL_KT (64  * FL_QROW)
#define FL_VT (128 * FL_VROW)
#define FL_STG (2 * FL_KT + 2 * FL_VT)
#define FL_SMEM (2 * FL_QT + 2 * FL_STG)

__device__ __forceinline__ void cp_rows(const bf16* __restrict__ g, int ldg,
                                        int row0, int col0, uint32_t sdst,
                                        int stride, int cps_per_row, int nops, int t) {
    for (int o = t; o < nops; o += 256) {
        int r = o / cps_per_row, c = o % cps_per_row;
        CP16(sdst + r * stride + c * 16,
             g + (long long)(row0 + r) * ldg + col0 + c * 8);
    }
}

__global__ __launch_bounds__(256) void flash_k(
    const bf16* __restrict__ qh, const bf16* __restrict__ ql,
    const bf16* __restrict__ kh, const bf16* __restrict__ kl,
    const bf16* __restrict__ vth, const bf16* __restrict__ vtl,
    bf16* __restrict__ oh, bf16* __restrict__ ol)
{
    int id = blockIdx.x;
    int qb = 15 - (id >> 4);           // heavy q-blocks scheduled first
    int h = id & 15;
    int kvh = h >> 2;
    int q0 = qb * 128;

    extern __shared__ char sm[];
    uint32_t S = smem_u32(sm);
    uint32_t smQ = S;
    int t = threadIdx.x, w = t >> 5, l = t & 31;
    int g = l >> 2, tg = l & 3;

    cp_rows(qh, HID, q0, h * 128, smQ,         FL_QROW, 16, 2048, t);
    cp_rows(ql, HID, q0, h * 128, smQ + FL_QT, FL_QROW, 16, 2048, t);
    {
        uint32_t st = S + 2 * FL_QT;
        cp_rows(kh, 512, 0, kvh * 128, st,                      FL_QROW, 16, 1024, t);
        cp_rows(kl, 512, 0, kvh * 128, st + FL_KT,              FL_QROW, 16, 1024, t);
        cp_rows(vth, S_LEN, kvh * 128, 0, st + 2 * FL_KT,         FL_VROW, 8, 1024, t);
        cp_rows(vtl, S_LEN, kvh * 128, 0, st + 2 * FL_KT + FL_VT, FL_VROW, 8, 1024, t);
    }
    CP_COMMIT();

    float acc[16][4];
#pragma unroll
    for (int nf = 0; nf < 16; nf++)
#pragma unroll
        for (int c = 0; c < 4; c++) acc[nf][c] = 0.f;
    float m0 = -1e30f, m1 = -1e30f, l0 = 0.f, l1 = 0.f;

    int niter = 2 * qb + 2;

    int a_row = w * 16 + (l & 15);
    int a_kb  = ((l >> 4) & 1) * 16;
    int b_sub = (l & 7) + ((l >> 4) & 1) * 8;
    int b_kb  = ((l >> 3) & 1) * 16;

    for (int jj = 0; jj < niter; jj++) {
        if (jj + 1 < niter) {
            uint32_t st = S + 2 * FL_QT + ((jj + 1) & 1) * FL_STG;
            int k0 = (jj + 1) * 64;
            cp_rows(kh, 512, k0, kvh * 128, st,                      FL_QROW, 16, 1024, t);
            cp_rows(kl, 512, k0, kvh * 128, st + FL_KT,              FL_QROW, 16, 1024, t);
            cp_rows(vth, S_LEN, kvh * 128, k0, st + 2 * FL_KT,         FL_VROW, 8, 1024, t);
            cp_rows(vtl, S_LEN, kvh * 128, k0, st + 2 * FL_KT + FL_VT, FL_VROW, 8, 1024, t);
            CP_COMMIT();
            CP_WAIT1();
        } else {
            CP_WAIT0();
        }
        __syncthreads();

        bool active = !(jj == 2 * qb + 1 && w < 4);
        if (active) {
            uint32_t base = S + 2 * FL_QT + (jj & 1) * FL_STG;
            uint32_t bKh = base, bVh = base + 2 * FL_KT;

            float sf[8][4];
#pragma unroll
            for (int nf = 0; nf < 8; nf++)
#pragma unroll
                for (int c = 0; c < 4; c++) sf[nf][c] = 0.f;

            // ---- S = Q K^T (3-term split), term-outer for ILP ----
#pragma unroll
            for (int ks = 0; ks < 8; ks++) {
                uint32_t aaddr = smQ + a_row * FL_QROW + ks * 32 + a_kb;
                uint32_t ah[4], al[4], bh[8][2], bl[8][2];
                ldsm_x4(ah[0], ah[1], ah[2], ah[3], aaddr);
                ldsm_x4(al[0], al[1], al[2], al[3], aaddr + FL_QT);
#pragma unroll
                for (int p = 0; p < 4; p++) {
                    uint32_t baddr = bKh + (p * 16 + b_sub) * FL_QROW + ks * 32 + b_kb;
                    uint32_t r0, r1, r2, r3;
                    ldsm_x4(r0, r1, r2, r3, baddr);
                    bh[2 * p][0] = r0;     bh[2 * p][1] = r1;
                    bh[2 * p + 1][0] = r2; bh[2 * p + 1][1] = r3;
                    ldsm_x4(r0, r1, r2, r3, baddr + FL_KT);
                    bl[2 * p][0] = r0;     bl[2 * p][1] = r1;
                    bl[2 * p + 1][0] = r2; bl[2 * p + 1][1] = r3;
                }
#pragma unroll
                for (int nf = 0; nf < 8; nf++) hmma(sf[nf], ah, bh[nf]);
#pragma unroll
                for (int nf = 0; nf < 8; nf++) hmma(sf[nf], al, bh[nf]);
#pragma unroll
                for (int nf = 0; nf < 8; nf++) hmma(sf[nf], ah, bl[nf]);
            }

            // ---- causal mask (diag blocks only) ----
            if (jj >= 2 * qb) {
                int r0g = q0 + w * 16 + g;
#pragma unroll
                for (int nf = 0; nf < 8; nf++) {
                    int cg = jj * 64 + nf * 8 + 2 * tg;
                    if (cg     > r0g)     sf[nf][0] = -1e30f;
                    if (cg + 1 > r0g)     sf[nf][1] = -1e30f;
                    if (cg     > r0g + 8) sf[nf][2] = -1e30f;
                    if (cg + 1 > r0g + 8) sf[nf][3] = -1e30f;
                }
            }

            // ---- online softmax (base-2) ----
            float mx0 = m0, mx1 = m1;
#pragma unroll
            for (int nf = 0; nf < 8; nf++) {
                mx0 = fmaxf(mx0, fmaxf(sf[nf][0], sf[nf][1]));
                mx1 = fmaxf(mx1, fmaxf(sf[nf][2], sf[nf][3]));
            }
            mx0 = fmaxf(mx0, __shfl_xor_sync(0xffffffffu, mx0, 1));
            mx0 = fmaxf(mx0, __shfl_xor_sync(0xffffffffu, mx0, 2));
            mx1 = fmaxf(mx1, __shfl_xor_sync(0xffffffffu, mx1, 1));
            mx1 = fmaxf(mx1, __shfl_xor_sync(0xffffffffu, mx1, 2));
            float al0 = ex2(m0 - mx0), al1 = ex2(m1 - mx1);
            m0 = mx0; m1 = mx1;
            l0 *= al0; l1 *= al1;
#pragma unroll
            for (int nf = 0; nf < 8; nf++) {
                float p0 = ex2(sf[nf][0] - m0);
                float p1 = ex2(sf[nf][1] - m0);
                float p2 = ex2(sf[nf][2] - m1);
                float p3 = ex2(sf[nf][3] - m1);
                sf[nf][0] = p0; sf[nf][1] = p1; sf[nf][2] = p2; sf[nf][3] = p3;
                l0 += p0 + p1; l1 += p2 + p3;
            }
#pragma unroll
            for (int nf = 0; nf < 16; nf++) {
                acc[nf][0] *= al0; acc[nf][1] *= al0;
                acc[nf][2] *= al1; acc[nf][3] *= al1;
            }

            // ---- PV: acc += P V (3-term split), P packed in registers ----
#pragma unroll
            for (int u = 0; u < 4; u++) {
                uint32_t ph[4], pl[4];
                {
                    float e00 = sf[2 * u][0],     e01 = sf[2 * u][1];
                    float e10 = sf[2 * u][2],     e11 = sf[2 * u][3];
                    float e20 = sf[2 * u + 1][0], e21 = sf[2 * u + 1][1];
                    float e30 = sf[2 * u + 1][2], e31 = sf[2 * u + 1][3];
                    ph[0] = prmt_hi(__float_as_uint(e00), __float_as_uint(e01));
                    ph[1] = prmt_hi(__float_as_uint(e10), __float_as_uint(e11));
                    ph[2] = prmt_hi(__float_as_uint(e20), __float_as_uint(e21));
                    ph[3] = prmt_hi(__float_as_uint(e30), __float_as_uint(e31));
                    pl[0] = pack_bf16(e00 - trunc_bf(e00), e01 - trunc_bf(e01));
                    pl[1] = pack_bf16(e10 - trunc_bf(e10), e11 - trunc_bf(e11));
                    pl[2] = pack_bf16(e20 - trunc_bf(e20), e21 - trunc_bf(e21));
                    pl[3] = pack_bf16(e30 - trunc_bf(e30), e31 - trunc_bf(e31));
                }
#pragma unroll
                for (int p = 0; p < 8; p++) {
                    uint32_t vaddr = bVh + (p * 16 + b_sub) * FL_VROW + u * 32 + b_kb;
                    uint32_t r0, r1, r2, r3, s0, s1, s2, s3;
                    ldsm_x4(r0, r1, r2, r3, vaddr);
                    ldsm_x4(s0, s1, s2, s3, vaddr + FL_VT);
                    uint32_t vh0[2] = {r0, r1}, vh1[2] = {r2, r3};
                    uint32_t vl0[2] = {s0, s1}, vl1[2] = {s2, s3};
                    hmma(acc[2 * p],     ph, vh0);
                    hmma(acc[2 * p + 1], ph, vh1);
                    hmma(acc[2 * p],     pl, vh0);
                    hmma(acc[2 * p + 1], pl, vh1);
                    hmma(acc[2 * p],     ph, vl0);
                    hmma(acc[2 * p + 1], ph, vl1);
                }
            }
        }
        __syncthreads();
    }

    l0 += __shfl_xor_sync(0xffffffffu, l0, 1);
    l0 += __shfl_xor_sync(0xffffffffu, l0, 2);
    l1 += __shfl_xor_sync(0xffffffffu, l1, 1);
    l1 += __shfl_xor_sync(0xffffffffu, l1, 2);
    float i0 = 1.f / l0, i1 = 1.f / l1;
    int row0 = q0 + w * 16 + g;
#pragma unroll
    for (int nf = 0; nf < 16; nf++) {
        int col = h * 128 + nf * 8 + 2 * tg;
        float o0 = acc[nf][0] * i0, o1 = acc[nf][1] * i0;
        float o2 = acc[nf][2] * i1, o3 = acc[nf][3] * i1;
        uint32_t hw0 = pack_bf16(o0, o1);
        uint32_t hw1 = pack_bf16(o2, o3);
        float h00 = __uint_as_float(hw0 << 16), h01 = __uint_as_float(hw0 & 0xFFFF0000u);
        float h10 = __uint_as_float(hw1 << 16), h11 = __uint_as_float(hw1 & 0xFFFF0000u);
        uint32_t lw0 = pack_bf16(o0 - h00, o1 - h01);
        uint32_t lw1 = pack_bf16(o2 - h10, o3 - h11);
        *(uint32_t*)&oh[(long long)row0 * HID + col]       = hw0;
        *(uint32_t*)&ol[(long long)row0 * HID + col]       = lw0;
        *(uint32_t*)&oh[(long long)(row0 + 8) * HID + col] = hw1;
        *(uint32_t*)&ol[(long long)(row0 + 8) * HID + col] = lw1;
    }
}

// ---------------------------------------------------------------------------
__global__ __launch_bounds__(256) void conv_k(const float* __restrict__ x,
                                              bf16* __restrict__ h, bf16* __restrict__ l, int n)
{
    int i = blockIdx.x * 256 + threadIdx.x;
    if (i >= n) return;
    float v = x[i];
    bf16 a = __float2bfloat16(v);
    h[i] = a;
    l[i] = __float2bfloat16(v - __bfloat162float(a));
}

__global__ __launch_bounds__(256) void transconv_k(const float* __restrict__ src, int sld,
                                                   int scol0, bf16* __restrict__ dh,
                                                   bf16* __restrict__ dl, int dld)
{
    __shared__ float tile[32][33];
    int tx = threadIdx.x, ty = threadIdx.y;
    int sr = blockIdx.x * 32;
    int sc = blockIdx.y * 32;
#pragma unroll
    for (int k = 0; k < 32; k += 8)
        tile[ty + k][tx] = src[(long long)(sr + ty + k) * sld + scol0 + sc + tx];
    __syncthreads();
#pragma unroll
    for (int k = 0; k < 32; k += 8) {
        float v = tile[tx][ty + k];
        bf16 h = __float2bfloat16(v);
        long long o = (long long)(sc + ty + k) * dld + sr + tx;
        dh[o] = h;
        dl[o] = __float2bfloat16(v - __bfloat162float(h));
    }
}

__global__ __launch_bounds__(256) void rope_split_k(const float* __restrict__ qkv,
    bf16* __restrict__ qh, bf16* __restrict__ ql,
    bf16* __restrict__ kh, bf16* __restrict__ kl)
{
    int idx = blockIdx.x * 256 + threadIdx.x;
    int i  = idx & 63;
    int hh = (idx >> 6) % 20;
    int s  = idx / (64 * 20);
    const float* p = qkv + (long long)s * QKV_N + ((hh < 16) ? hh * 128 : 2048 + (hh - 16) * 128);

    float f  = (float)s * __expf((float)i * -0.14391156831212787f);
    float sf = sinf(f), cf = cosf(f);
    float x1 = p[i], x2 = p[i + 64];
    float y1 = x1 * cosf(sf) - x2 * sinf(sf);
    float y2 = x2 * cosf(cf) + x1 * sinf(cf);

    if (hh < 16) {
        y1 *= QSCALE; y2 *= QSCALE;
        long long o = (long long)s * HID + hh * 128 + i;
        bf16 a = __float2bfloat16(y1);
        qh[o] = a; ql[o] = __float2bfloat16(y1 - __bfloat162float(a));
        bf16 b = __float2bfloat16(y2);
        qh[o + 64] = b; ql[o + 64] = __float2bfloat16(y2 - __bfloat162float(b));
    } else {
        long long o = (long long)s * 512 + (hh - 16) * 128 + i;
        bf16 a = __float2bfloat16(y1);
        kh[o] = a; kl[o] = __float2bfloat16(y1 - __bfloat162float(a));
        bf16 b = __float2bfloat16(y2);
        kh[o + 64] = b; kl[o + 64] = __float2bfloat16(y2 - __bfloat162float(b));
    }
}

// ---------------------------------------------------------------------------
extern "C" void kernel_launch(void* const* d_in, const int* in_sizes, int n_in,
                              void* d_out, int out_size)
{
    const float* hidden = (const float*)d_in[0];
    const float* W_attn = (const float*)d_in[3];
    const float* W_proj = (const float*)d_in[4];
    float* out = (float*)d_out;

    float* qkv;
    bf16 *xh, *xl, *wh, *wl, *w2h, *w2l, *qh, *ql, *kh, *kl, *vth, *vtl;
    cudaGetSymbolAddress((void**)&qkv, g_qkv);
    cudaGetSymbolAddress((void**)&xh, g_xh);   cudaGetSymbolAddress((void**)&xl, g_xl);
    cudaGetSymbolAddress((void**)&wh, g_wh);   cudaGetSymbolAddress((void**)&wl, g_wl);
    cudaGetSymbolAddress((void**)&w2h, g_w2h); cudaGetSymbolAddress((void**)&w2l, g_w2l);
    cudaGetSymbolAddress((void**)&qh, g_qh);   cudaGetSymbolAddress((void**)&ql, g_ql);
    cudaGetSymbolAddress((void**)&kh, g_kh);   cudaGetSymbolAddress((void**)&kl, g_kl);
    cudaGetSymbolAddress((void**)&vth, g_vth); cudaGetSymbolAddress((void**)&vtl, g_vtl);

    cudaFuncSetAttribute(gemm_bb3, cudaFuncAttributeMaxDynamicSharedMemorySize, GEMM_SMEM);
    cudaFuncSetAttribute(flash_k, cudaFuncAttributeMaxDynamicSharedMemorySize, FL_SMEM);

    // 1) splits (W_proj done early; gemm_QKV lands in the ncu capture window)
    conv_k<<<(S_LEN * HID) / 256, 256>>>(hidden, xh, xl, S_LEN * HID);
    transconv_k<<<dim3(64, 96), dim3(32, 8)>>>(W_attn, QKV_N, 0, wh, wl, HID);
    transconv_k<<<dim3(64, 64), dim3(32, 8)>>>(W_proj, HID, 0, w2h, w2l, HID);

    // 2) qkv = hidden @ W_attn
    gemm_bb3<<<dim3(QKV_N / 128, S_LEN / 128), 256, GEMM_SMEM>>>(
        xh, xl, HID, wh, wl, HID, qkv, QKV_N, HID);

    // 3) rope + split q/k ; transpose+split v
    rope_split_k<<<(S_LEN * 20 * 64) / 256, 256>>>(qkv, qh, ql, kh, kl);
    transconv_k<<<dim3(64, 16), dim3(32, 8)>>>(qkv, QKV_N, 2560, vth, vtl, S_LEN);

    // 4) fused flash attention -> split bf16 attn (xh, xl)
    flash_k<<<256, 256, FL_SMEM>>>(qh, ql, kh, kl, vth, vtl, xh, xl);

    // 5) out = attn @ W_proj
    gemm_bb3<<<dim3(HID / 128, S_LEN / 128), 256, GEMM_SMEM>>>(
        xh, xl, HID, w2h, w2l, HID, out, HID, HID);
}

// round 6
// speedup vs baseline: 4.0749x; 1.0576x over previous
#include <cuda_runtime.h>
#include <cuda_bf16.h>
#include <cstdint>

typedef __nv_bfloat16 bf16;

#define S_LEN 2048
#define HID   2048
#define QKV_N 3072
#define NH    16
// q scale with log2(e) folded in (flash softmax runs in base-2)
#define QSCALE (0.08838834764831845f * 1.4426950408889634f)

// ---------------- scratch (static device allocations) ----------------
__device__ float g_qkv[S_LEN * QKV_N];
__device__ bf16  g_xh[S_LEN * HID], g_xl[S_LEN * HID];   // hidden split, then attn split
__device__ bf16  g_wh[QKV_N * HID], g_wl[QKV_N * HID];   // W_attn^T split
__device__ bf16  g_w2h[HID * HID],  g_w2l[HID * HID];    // W_proj^T split
__device__ bf16  g_qh[S_LEN * HID], g_ql[S_LEN * HID];
__device__ bf16  g_kh[S_LEN * 512], g_kl[S_LEN * 512];
__device__ bf16  g_vth[512 * S_LEN], g_vtl[512 * S_LEN]; // V^T per kv head

// ---------------- helpers ----------------
__device__ __forceinline__ uint32_t smem_u32(const void* p) {
    uint32_t a;
    asm("{ .reg .u64 t; cvta.to.shared.u64 t, %1; cvt.u32.u64 %0, t; }" : "=r"(a) : "l"(p));
    return a;
}
#define CP16(dst, src) \
    asm volatile("cp.async.cg.shared.global [%0], [%1], 16;" :: "r"(dst), "l"(src))
#define CP_COMMIT() asm volatile("cp.async.commit_group;" ::: "memory")
#define CP_WAIT1()  asm volatile("cp.async.wait_group 1;" ::: "memory")
#define CP_WAIT0()  asm volatile("cp.async.wait_group 0;" ::: "memory")

__device__ __forceinline__ void ldsm_x4(uint32_t& r0, uint32_t& r1, uint32_t& r2,
                                        uint32_t& r3, uint32_t a) {
    asm volatile("ldmatrix.sync.aligned.m8n8.x4.shared.b16 {%0,%1,%2,%3}, [%4];"
                 : "=r"(r0), "=r"(r1), "=r"(r2), "=r"(r3) : "r"(a));
}
__device__ __forceinline__ void hmma(float* d, const uint32_t* a, const uint32_t* b) {
    asm volatile("mma.sync.aligned.m16n8k16.row.col.f32.bf16.bf16.f32 "
                 "{%0,%1,%2,%3}, {%4,%5,%6,%7}, {%8,%9}, {%0,%1,%2,%3};"
                 : "+f"(d[0]), "+f"(d[1]), "+f"(d[2]), "+f"(d[3])
                 : "r"(a[0]), "r"(a[1]), "r"(a[2]), "r"(a[3]), "r"(b[0]), "r"(b[1]));
}
__device__ __forceinline__ float ex2(float x) {
    float r; asm("ex2.approx.f32 %0, %1;" : "=f"(r) : "f"(x)); return r;
}
__device__ __forceinline__ uint32_t pack_bf16(float e_lo, float e_hi) {
    uint32_t r;
    asm("cvt.rn.bf16x2.f32 %0, %1, %2;" : "=r"(r) : "f"(e_hi), "f"(e_lo));
    return r;
}
__device__ __forceinline__ uint32_t prmt_hi(uint32_t a, uint32_t b) {
    uint32_t r; asm("prmt.b32 %0, %1, %2, 0x7632;" : "=r"(r) : "r"(a), "r"(b)); return r;
}
__device__ __forceinline__ float trunc_bf(float x) {
    return __uint_as_float(__float_as_uint(x) & 0xFFFF0000u);
}

// ---------------------------------------------------------------------------
// 3-term split-bf16 GEMM via mma.sync: C = A @ B^T, B is [N][K]
// 128 threads (4 warps, 2x2 warp grid, warp tile 32x64), BM=64, BN=128, BK=32.
// Stage smem 30720 B, double-buffered -> 61440 B/CTA -> 3 CTAs/SM, 12 warps.
// ---------------------------------------------------------------------------
#define TROW    80
#define A_TB    (64  * TROW)           // 5120 B  (one A tile, 64 rows)
#define B_TB    (128 * TROW)           // 10240 B (one B tile, 128 rows)
#define STAGE_B (2 * A_TB + 2 * B_TB)  // 30720 B (Ah, Al, Bh, Bl)
#define GEMM_SMEM (2 * STAGE_B)        // 61440 B

__device__ __forceinline__ void tile_cp_n(const bf16* __restrict__ g, int ldg,
                                          int r0, int k0, uint32_t sdst,
                                          int nrows, int t) {
    int nops = nrows * 4;
    for (int o = t; o < nops; o += 128) {
        int row = o >> 2, c = o & 3;
        CP16(sdst + row * TROW + c * 16,
             g + (long long)(r0 + row) * ldg + k0 + c * 8);
    }
}

__global__ void __launch_bounds__(128, 3) gemm_bb3(
    const bf16* __restrict__ Ah, const bf16* __restrict__ Al, int lda,
    const bf16* __restrict__ Bh, const bf16* __restrict__ Bl, int ldb,
    float* __restrict__ C, int ldc, int K)
{
    int rb = blockIdx.y, cb = blockIdx.x;
    int row0 = rb * 64, col0 = cb * 128;

    extern __shared__ char sm[];
    uint32_t sbase = smem_u32(sm);
    int t = threadIdx.x, w = t >> 5, l = t & 31;
    int wm = w & 1, wn = w >> 1;       // warp tile: rows wm*32, cols wn*64

    float acc[2][8][4];
#pragma unroll
    for (int i = 0; i < 2; i++)
#pragma unroll
        for (int j = 0; j < 8; j++)
#pragma unroll
            for (int q = 0; q < 4; q++) acc[i][j][q] = 0.f;

    int niter = K / 32;
    uint32_t stg[2] = {sbase, sbase + STAGE_B};

    tile_cp_n(Ah, lda, row0, 0, stg[0],              64,  t);
    tile_cp_n(Al, lda, row0, 0, stg[0] + A_TB,       64,  t);
    tile_cp_n(Bh, ldb, col0, 0, stg[0] + 2 * A_TB,        128, t);
    tile_cp_n(Bl, ldb, col0, 0, stg[0] + 2 * A_TB + B_TB, 128, t);
    CP_COMMIT();

    int a_row = wm * 32 + (l & 15);
    int a_kb  = ((l >> 4) & 1) * 16;
    int b_row = wn * 64 + (l & 7) + ((l >> 4) & 1) * 8;
    int b_kb  = ((l >> 3) & 1) * 16;

    for (int it = 0; it < niter; it++) {
        if (it + 1 < niter) {
            uint32_t nb = stg[(it + 1) & 1];
            int k0 = (it + 1) * 32;
            tile_cp_n(Ah, lda, row0, k0, nb,              64,  t);
            tile_cp_n(Al, lda, row0, k0, nb + A_TB,       64,  t);
            tile_cp_n(Bh, ldb, col0, k0, nb + 2 * A_TB,        128, t);
            tile_cp_n(Bl, ldb, col0, k0, nb + 2 * A_TB + B_TB, 128, t);
            CP_COMMIT();
            CP_WAIT1();
        } else {
            CP_WAIT0();
        }
        __syncthreads();

        uint32_t base = stg[it & 1];
#pragma unroll
        for (int ks = 0; ks < 2; ks++) {
            int kbyte = ks * 32;
            uint32_t ah[2][4], al[2][4], bh[8][2], bl[8][2];
#pragma unroll
            for (int mf = 0; mf < 2; mf++) {
                uint32_t aaddr = base + (a_row + mf * 16) * TROW + kbyte + a_kb;
                ldsm_x4(ah[mf][0], ah[mf][1], ah[mf][2], ah[mf][3], aaddr);
                ldsm_x4(al[mf][0], al[mf][1], al[mf][2], al[mf][3], aaddr + A_TB);
            }
#pragma unroll
            for (int p = 0; p < 4; p++) {
                uint32_t baddr = base + 2 * A_TB + (b_row + p * 16) * TROW + kbyte + b_kb;
                uint32_t r0, r1, r2, r3;
                ldsm_x4(r0, r1, r2, r3, baddr);
                bh[2 * p][0] = r0;     bh[2 * p][1] = r1;
                bh[2 * p + 1][0] = r2; bh[2 * p + 1][1] = r3;
                ldsm_x4(r0, r1, r2, r3, baddr + B_TB);
                bl[2 * p][0] = r0;     bl[2 * p][1] = r1;
                bl[2 * p + 1][0] = r2; bl[2 * p + 1][1] = r3;
            }
            // term-outer: 16 independent MMAs per sweep (no same-acc chains)
#pragma unroll
            for (int mf = 0; mf < 2; mf++)
#pragma unroll
                for (int nf = 0; nf < 8; nf++) hmma(acc[mf][nf], ah[mf], bh[nf]);
#pragma unroll
            for (int mf = 0; mf < 2; mf++)
#pragma unroll
                for (int nf = 0; nf < 8; nf++) hmma(acc[mf][nf], al[mf], bh[nf]);
#pragma unroll
            for (int mf = 0; mf < 2; mf++)
#pragma unroll
                for (int nf = 0; nf < 8; nf++) hmma(acc[mf][nf], ah[mf], bl[nf]);
        }
        __syncthreads();
    }

#pragma unroll
    for (int mf = 0; mf < 2; mf++) {
        int r_lo = row0 + wm * 32 + mf * 16 + (l >> 2);
#pragma unroll
        for (int nf = 0; nf < 8; nf++) {
            int cix = col0 + wn * 64 + nf * 8 + (l & 3) * 2;
            *(float2*)&C[(long long)r_lo * ldc + cix] =
                make_float2(acc[mf][nf][0], acc[mf][nf][1]);
            *(float2*)&C[(long long)(r_lo + 8) * ldc + cix] =
                make_float2(acc[mf][nf][2], acc[mf][nf][3]);
        }
    }
}

// ---------------------------------------------------------------------------
// Fused flash attention via mma.sync. One CTA = (head, 128-row q block).
// Heavy-first CTA mapping for load balance.
// ---------------------------------------------------------------------------
#define FL_QROW 272
#define FL_VROW 144
#define FL_QT (128 * FL_QROW)
#define FL_KT (64  * FL_QROW)
#define FL_VT (128 * FL_VROW)
#define FL_STG (2 * FL_KT + 2 * FL_VT)
#define FL_SMEM (2 * FL_QT + 2 * FL_STG)

__device__ __forceinline__ void cp_rows(const bf16* __restrict__ g, int ldg,
                                        int row0, int col0, uint32_t sdst,
                                        int stride, int cps_per_row, int nops, int t) {
    for (int o = t; o < nops; o += 256) {
        int r = o / cps_per_row, c = o % cps_per_row;
        CP16(sdst + r * stride + c * 16,
             g + (long long)(row0 + r) * ldg + col0 + c * 8);
    }
}

__global__ __launch_bounds__(256) void flash_k(
    const bf16* __restrict__ qh, const bf16* __restrict__ ql,
    const bf16* __restrict__ kh, const bf16* __restrict__ kl,
    const bf16* __restrict__ vth, const bf16* __restrict__ vtl,
    bf16* __restrict__ oh, bf16* __restrict__ ol)
{
    int id = blockIdx.x;
    int qb = 15 - (id >> 4);           // heavy q-blocks scheduled first
    int h = id & 15;
    int kvh = h >> 2;
    int q0 = qb * 128;

    extern __shared__ char sm[];
    uint32_t S = smem_u32(sm);
    uint32_t smQ = S;
    int t = threadIdx.x, w = t >> 5, l = t & 31;
    int g = l >> 2, tg = l & 3;

    cp_rows(qh, HID, q0, h * 128, smQ,         FL_QROW, 16, 2048, t);
    cp_rows(ql, HID, q0, h * 128, smQ + FL_QT, FL_QROW, 16, 2048, t);
    {
        uint32_t st = S + 2 * FL_QT;
        cp_rows(kh, 512, 0, kvh * 128, st,                      FL_QROW, 16, 1024, t);
        cp_rows(kl, 512, 0, kvh * 128, st + FL_KT,              FL_QROW, 16, 1024, t);
        cp_rows(vth, S_LEN, kvh * 128, 0, st + 2 * FL_KT,         FL_VROW, 8, 1024, t);
        cp_rows(vtl, S_LEN, kvh * 128, 0, st + 2 * FL_KT + FL_VT, FL_VROW, 8, 1024, t);
    }
    CP_COMMIT();

    float acc[16][4];
#pragma unroll
    for (int nf = 0; nf < 16; nf++)
#pragma unroll
        for (int c = 0; c < 4; c++) acc[nf][c] = 0.f;
    float m0 = -1e30f, m1 = -1e30f, l0 = 0.f, l1 = 0.f;

    int niter = 2 * qb + 2;

    int a_row = w * 16 + (l & 15);
    int a_kb  = ((l >> 4) & 1) * 16;
    int b_sub = (l & 7) + ((l >> 4) & 1) * 8;
    int b_kb  = ((l >> 3) & 1) * 16;

    for (int jj = 0; jj < niter; jj++) {
        if (jj + 1 < niter) {
            uint32_t st = S + 2 * FL_QT + ((jj + 1) & 1) * FL_STG;
            int k0 = (jj + 1) * 64;
            cp_rows(kh, 512, k0, kvh * 128, st,                      FL_QROW, 16, 1024, t);
            cp_rows(kl, 512, k0, kvh * 128, st + FL_KT,              FL_QROW, 16, 1024, t);
            cp_rows(vth, S_LEN, kvh * 128, k0, st + 2 * FL_KT,         FL_VROW, 8, 1024, t);
            cp_rows(vtl, S_LEN, kvh * 128, k0, st + 2 * FL_KT + FL_VT, FL_VROW, 8, 1024, t);
            CP_COMMIT();
            CP_WAIT1();
        } else {
            CP_WAIT0();
        }
        __syncthreads();

        bool active = !(jj == 2 * qb + 1 && w < 4);
        if (active) {
            uint32_t base = S + 2 * FL_QT + (jj & 1) * FL_STG;
            uint32_t bKh = base, bVh = base + 2 * FL_KT;

            float sf[8][4];
#pragma unroll
            for (int nf = 0; nf < 8; nf++)
#pragma unroll
                for (int c = 0; c < 4; c++) sf[nf][c] = 0.f;

            // ---- S = Q K^T (3-term split), term-outer for ILP ----
#pragma unroll
            for (int ks = 0; ks < 8; ks++) {
                uint32_t aaddr = smQ + a_row * FL_QROW + ks * 32 + a_kb;
                uint32_t ah[4], al[4], bh[8][2], bl[8][2];
                ldsm_x4(ah[0], ah[1], ah[2], ah[3], aaddr);
                ldsm_x4(al[0], al[1], al[2], al[3], aaddr + FL_QT);
#pragma unroll
                for (int p = 0; p < 4; p++) {
                    uint32_t baddr = bKh + (p * 16 + b_sub) * FL_QROW + ks * 32 + b_kb;
                    uint32_t r0, r1, r2, r3;
                    ldsm_x4(r0, r1, r2, r3, baddr);
                    bh[2 * p][0] = r0;     bh[2 * p][1] = r1;
                    bh[2 * p + 1][0] = r2; bh[2 * p + 1][1] = r3;
                    ldsm_x4(r0, r1, r2, r3, baddr + FL_KT);
                    bl[2 * p][0] = r0;     bl[2 * p][1] = r1;
                    bl[2 * p + 1][0] = r2; bl[2 * p + 1][1] = r3;
                }
#pragma unroll
                for (int nf = 0; nf < 8; nf++) hmma(sf[nf], ah, bh[nf]);
#pragma unroll
                for (int nf = 0; nf < 8; nf++) hmma(sf[nf], al, bh[nf]);
#pragma unroll
                for (int nf = 0; nf < 8; nf++) hmma(sf[nf], ah, bl[nf]);
            }

            // ---- causal mask (diag blocks only) ----
            if (jj >= 2 * qb) {
                int r0g = q0 + w * 16 + g;
#pragma unroll
                for (int nf = 0; nf < 8; nf++) {
                    int cg = jj * 64 + nf * 8 + 2 * tg;
                    if (cg     > r0g)     sf[nf][0] = -1e30f;
                    if (cg + 1 > r0g)     sf[nf][1] = -1e30f;
                    if (cg     > r0g + 8) sf[nf][2] = -1e30f;
                    if (cg + 1 > r0g + 8) sf[nf][3] = -1e30f;
                }
            }

            // ---- online softmax (base-2) ----
            float mx0 = m0, mx1 = m1;
#pragma unroll
            for (int nf = 0; nf < 8; nf++) {
                mx0 = fmaxf(mx0, fmaxf(sf[nf][0], sf[nf][1]));
                mx1 = fmaxf(mx1, fmaxf(sf[nf][2], sf[nf][3]));
            }
            mx0 = fmaxf(mx0, __shfl_xor_sync(0xffffffffu, mx0, 1));
            mx0 = fmaxf(mx0, __shfl_xor_sync(0xffffffffu, mx0, 2));
            mx1 = fmaxf(mx1, __shfl_xor_sync(0xffffffffu, mx1, 1));
            mx1 = fmaxf(mx1, __shfl_xor_sync(0xffffffffu, mx1, 2));
            float al0 = ex2(m0 - mx0), al1 = ex2(m1 - mx1);
            m0 = mx0; m1 = mx1;
            l0 *= al0; l1 *= al1;
#pragma unroll
            for (int nf = 0; nf < 8; nf++) {
                float p0 = ex2(sf[nf][0] - m0);
                float p1 = ex2(sf[nf][1] - m0);
                float p2 = ex2(sf[nf][2] - m1);
                float p3 = ex2(sf[nf][3] - m1);
                sf[nf][0] = p0; sf[nf][1] = p1; sf[nf][2] = p2; sf[nf][3] = p3;
                l0 += p0 + p1; l1 += p2 + p3;
            }
#pragma unroll
            for (int nf = 0; nf < 16; nf++) {
                acc[nf][0] *= al0; acc[nf][1] *= al0;
                acc[nf][2] *= al1; acc[nf][3] *= al1;
            }

            // ---- PV: acc += P V (3-term split), P packed in registers ----
#pragma unroll
            for (int u = 0; u < 4; u++) {
                uint32_t ph[4], pl[4];
                {
                    float e00 = sf[2 * u][0],     e01 = sf[2 * u][1];
                    float e10 = sf[2 * u][2],     e11 = sf[2 * u][3];
                    float e20 = sf[2 * u + 1][0], e21 = sf[2 * u + 1][1];
                    float e30 = sf[2 * u + 1][2], e31 = sf[2 * u + 1][3];
                    ph[0] = prmt_hi(__float_as_uint(e00), __float_as_uint(e01));
                    ph[1] = prmt_hi(__float_as_uint(e10), __float_as_uint(e11));
                    ph[2] = prmt_hi(__float_as_uint(e20), __float_as_uint(e21));
                    ph[3] = prmt_hi(__float_as_uint(e30), __float_as_uint(e31));
                    pl[0] = pack_bf16(e00 - trunc_bf(e00), e01 - trunc_bf(e01));
                    pl[1] = pack_bf16(e10 - trunc_bf(e10), e11 - trunc_bf(e11));
                    pl[2] = pack_bf16(e20 - trunc_bf(e20), e21 - trunc_bf(e21));
                    pl[3] = pack_bf16(e30 - trunc_bf(e30), e31 - trunc_bf(e31));
                }
#pragma unroll
                for (int p = 0; p < 8; p++) {
                    uint32_t vaddr = bVh + (p * 16 + b_sub) * FL_VROW + u * 32 + b_kb;
                    uint32_t r0, r1, r2, r3, s0, s1, s2, s3;
                    ldsm_x4(r0, r1, r2, r3, vaddr);
                    ldsm_x4(s0, s1, s2, s3, vaddr + FL_VT);
                    uint32_t vh0[2] = {r0, r1}, vh1[2] = {r2, r3};
                    uint32_t vl0[2] = {s0, s1}, vl1[2] = {s2, s3};
                    hmma(acc[2 * p],     ph, vh0);
                    hmma(acc[2 * p + 1], ph, vh1);
                    hmma(acc[2 * p],     pl, vh0);
                    hmma(acc[2 * p + 1], pl, vh1);
                    hmma(acc[2 * p],     ph, vl0);
                    hmma(acc[2 * p + 1], ph, vl1);
                }
            }
        }
        __syncthreads();
    }

    l0 += __shfl_xor_sync(0xffffffffu, l0, 1);
    l0 += __shfl_xor_sync(0xffffffffu, l0, 2);
    l1 += __shfl_xor_sync(0xffffffffu, l1, 1);
    l1 += __shfl_xor_sync(0xffffffffu, l1, 2);
    float i0 = 1.f / l0, i1 = 1.f / l1;
    int row0 = q0 + w * 16 + g;
#pragma unroll
    for (int nf = 0; nf < 16; nf++) {
        int col = h * 128 + nf * 8 + 2 * tg;
        float o0 = acc[nf][0] * i0, o1 = acc[nf][1] * i0;
        float o2 = acc[nf][2] * i1, o3 = acc[nf][3] * i1;
        uint32_t hw0 = pack_bf16(o0, o1);
        uint32_t hw1 = pack_bf16(o2, o3);
        float h00 = __uint_as_float(hw0 << 16), h01 = __uint_as_float(hw0 & 0xFFFF0000u);
        float h10 = __uint_as_float(hw1 << 16), h11 = __uint_as_float(hw1 & 0xFFFF0000u);
        uint32_t lw0 = pack_bf16(o0 - h00, o1 - h01);
        uint32_t lw1 = pack_bf16(o2 - h10, o3 - h11);
        *(uint32_t*)&oh[(long long)row0 * HID + col]       = hw0;
        *(uint32_t*)&ol[(long long)row0 * HID + col]       = lw0;
        *(uint32_t*)&oh[(long long)(row0 + 8) * HID + col] = hw1;
        *(uint32_t*)&ol[(long long)(row0 + 8) * HID + col] = lw1;
    }
}

// ---------------------------------------------------------------------------
__global__ __launch_bounds__(256) void conv_k(const float* __restrict__ x,
                                              bf16* __restrict__ h, bf16* __restrict__ l, int n)
{
    int i = blockIdx.x * 256 + threadIdx.x;
    if (i >= n) return;
    float v = x[i];
    bf16 a = __float2bfloat16(v);
    h[i] = a;
    l[i] = __float2bfloat16(v - __bfloat162float(a));
}

__global__ __launch_bounds__(256) void transconv_k(const float* __restrict__ src, int sld,
                                                   int scol0, bf16* __restrict__ dh,
                                                   bf16* __restrict__ dl, int dld)
{
    __shared__ float tile[32][33];
    int tx = threadIdx.x, ty = threadIdx.y;
    int sr = blockIdx.x * 32;
    int sc = blockIdx.y * 32;
#pragma unroll
    for (int k = 0; k < 32; k += 8)
        tile[ty + k][tx] = src[(long long)(sr + ty + k) * sld + scol0 + sc + tx];
    __syncthreads();
#pragma unroll
    for (int k = 0; k < 32; k += 8) {
        float v = tile[tx][ty + k];
        bf16 h = __float2bfloat16(v);
        long long o = (long long)(sc + ty + k) * dld + sr + tx;
        dh[o] = h;
        dl[o] = __float2bfloat16(v - __bfloat162float(h));
    }
}

__global__ __launch_bounds__(256) void rope_split_k(const float* __restrict__ qkv,
    bf16* __restrict__ qh, bf16* __restrict__ ql,
    bf16* __restrict__ kh, bf16* __restrict__ kl)
{
    int idx = blockIdx.x * 256 + threadIdx.x;
    int i  = idx & 63;
    int hh = (idx >> 6) % 20;
    int s  = idx / (64 * 20);
    const float* p = qkv + (long long)s * QKV_N + ((hh < 16) ? hh * 128 : 2048 + (hh - 16) * 128);

    float f  = (float)s * __expf((float)i * -0.14391156831212787f);
    float sf = sinf(f), cf = cosf(f);
    float x1 = p[i], x2 = p[i + 64];
    float y1 = x1 * cosf(sf) - x2 * sinf(sf);
    float y2 = x2 * cosf(cf) + x1 * sinf(cf);

    if (hh < 16) {
        y1 *= QSCALE; y2 *= QSCALE;
        long long o = (long long)s * HID + hh * 128 + i;
        bf16 a = __float2bfloat16(y1);
        qh[o] = a; ql[o] = __float2bfloat16(y1 - __bfloat162float(a));
        bf16 b = __float2bfloat16(y2);
        qh[o + 64] = b; ql[o + 64] = __float2bfloat16(y2 - __bfloat162float(b));
    } else {
        long long o = (long long)s * 512 + (hh - 16) * 128 + i;
        bf16 a = __float2bfloat16(y1);
        kh[o] = a; kl[o] = __float2bfloat16(y1 - __bfloat162float(a));
        bf16 b = __float2bfloat16(y2);
        kh[o + 64] = b; kl[o + 64] = __float2bfloat16(y2 - __bfloat162float(b));
    }
}

// ---------------------------------------------------------------------------
extern "C" void kernel_launch(void* const* d_in, const int* in_sizes, int n_in,
                              void* d_out, int out_size)
{
    const float* hidden = (const float*)d_in[0];
    const float* W_attn = (const float*)d_in[3];
    const float* W_proj = (const float*)d_in[4];
    float* out = (float*)d_out;

    float* qkv;
    bf16 *xh, *xl, *wh, *wl, *w2h, *w2l, *qh, *ql, *kh, *kl, *vth, *vtl;
    cudaGetSymbolAddress((void**)&qkv, g_qkv);
    cudaGetSymbolAddress((void**)&xh, g_xh);   cudaGetSymbolAddress((void**)&xl, g_xl);
    cudaGetSymbolAddress((void**)&wh, g_wh);   cudaGetSymbolAddress((void**)&wl, g_wl);
    cudaGetSymbolAddress((void**)&w2h, g_w2h); cudaGetSymbolAddress((void**)&w2l, g_w2l);
    cudaGetSymbolAddress((void**)&qh, g_qh);   cudaGetSymbolAddress((void**)&ql, g_ql);
    cudaGetSymbolAddress((void**)&kh, g_kh);   cudaGetSymbolAddress((void**)&kl, g_kl);
    cudaGetSymbolAddress((void**)&vth, g_vth); cudaGetSymbolAddress((void**)&vtl, g_vtl);

    cudaFuncSetAttribute(gemm_bb3, cudaFuncAttributeMaxDynamicSharedMemorySize, GEMM_SMEM);
    cudaFuncSetAttribute(flash_k, cudaFuncAttributeMaxDynamicSharedMemorySize, FL_SMEM);

    // 1) splits
    conv_k<<<(S_LEN * HID) / 256, 256>>>(hidden, xh, xl, S_LEN * HID);
    transconv_k<<<dim3(64, 96), dim3(32, 8)>>>(W_attn, QKV_N, 0, wh, wl, HID);
    transconv_k<<<dim3(64, 64), dim3(32, 8)>>>(W_proj, HID, 0, w2h, w2l, HID);

    // 2) qkv = hidden @ W_attn
    gemm_bb3<<<dim3(QKV_N / 128, S_LEN / 64), 128, GEMM_SMEM>>>(
        xh, xl, HID, wh, wl, HID, qkv, QKV_N, HID);

    // 3) rope + split q/k ; transpose+split v
    rope_split_k<<<(S_LEN * 20 * 64) / 256, 256>>>(qkv, qh, ql, kh, kl);
    transconv_k<<<dim3(64, 16), dim3(32, 8)>>>(qkv, QKV_N, 2560, vth, vtl, S_LEN);

    // 4) fused flash attention -> split bf16 attn (xh, xl)
    flash_k<<<256, 256, FL_SMEM>>>(qh, ql, kh, kl, vth, vtl, xh, xl);

    // 5) out = attn @ W_proj
    gemm_bb3<<<dim3(HID / 128, S_LEN / 64), 128, GEMM_SMEM>>>(
        xh, xl, HID, w2h, w2l, HID, out, HID, HID);
}

// round 7
// speedup vs baseline: 5.9409x; 1.4579x over previous
#include <cuda_runtime.h>
#include <cuda_fp16.h>
#include <cstdint>

typedef __half f16;

#define S_LEN 2048
#define HID   2048
#define QKV_N 3072
#define NH    16
// q scale with log2(e) folded in (flash softmax runs in base-2)
#define QSCALE (0.08838834764831845f * 1.4426950408889634f)

// ---------------- scratch (static device allocations) ----------------
__device__ float g_qkv[S_LEN * QKV_N];
__device__ f16  g_xh[S_LEN * HID], g_xl[S_LEN * HID];   // hidden split, then attn split
__device__ f16  g_wh[QKV_N * HID];                       // W_attn^T (single fp16)
__device__ f16  g_w2h[HID * HID];                        // W_proj^T (single fp16)
__device__ f16  g_qh[S_LEN * HID], g_ql[S_LEN * HID];
__device__ f16  g_kh[S_LEN * 512];
__device__ f16  g_vth[512 * S_LEN];                      // V^T per kv head

// ---------------- helpers ----------------
__device__ __forceinline__ uint32_t smem_u32(const void* p) {
    uint32_t a;
    asm("{ .reg .u64 t; cvta.to.shared.u64 t, %1; cvt.u32.u64 %0, t; }" : "=r"(a) : "l"(p));
    return a;
}
#define CP16(dst, src) \
    asm volatile("cp.async.cg.shared.global [%0], [%1], 16;" :: "r"(dst), "l"(src))
#define CP_COMMIT() asm volatile("cp.async.commit_group;" ::: "memory")
#define CP_WAIT1()  asm volatile("cp.async.wait_group 1;" ::: "memory")
#define CP_WAIT0()  asm volatile("cp.async.wait_group 0;" ::: "memory")

__device__ __forceinline__ void ldsm_x4(uint32_t& r0, uint32_t& r1, uint32_t& r2,
                                        uint32_t& r3, uint32_t a) {
    asm volatile("ldmatrix.sync.aligned.m8n8.x4.shared.b16 {%0,%1,%2,%3}, [%4];"
                 : "=r"(r0), "=r"(r1), "=r"(r2), "=r"(r3) : "r"(a));
}
__device__ __forceinline__ void hmma(float* d, const uint32_t* a, const uint32_t* b) {
    asm volatile("mma.sync.aligned.m16n8k16.row.col.f32.f16.f16.f32 "
                 "{%0,%1,%2,%3}, {%4,%5,%6,%7}, {%8,%9}, {%0,%1,%2,%3};"
                 : "+f"(d[0]), "+f"(d[1]), "+f"(d[2]), "+f"(d[3])
                 : "r"(a[0]), "r"(a[1]), "r"(a[2]), "r"(a[3]), "r"(b[0]), "r"(b[1]));
}
__device__ __forceinline__ float ex2(float x) {
    float r; asm("ex2.approx.f32 %0, %1;" : "=f"(r) : "f"(x)); return r;
}
__device__ __forceinline__ uint32_t pack_f16(float lo, float hi) {
    __half2 h = __floats2half2_rn(lo, hi);
    return *reinterpret_cast<uint32_t*>(&h);
}
__device__ __forceinline__ float2 unpack_f16(uint32_t w) {
    __half2 h = *reinterpret_cast<__half2*>(&w);
    return __half22float2(h);
}

// ---------------------------------------------------------------------------
// 2-term split-fp16 GEMM via mma.sync: C = (Ah+Al) @ Bh^T, B is [N][K]
// 128 threads (2x2 warp grid, warp tile 32x64), BM=64, BN=128, BK=32.
// Stage smem 20480 B, double-buffered -> 40960 B/CTA -> 4 CTAs/SM.
// ---------------------------------------------------------------------------
#define TROW    80
#define A_TB    (64  * TROW)           // 5120 B
#define B_TB    (128 * TROW)           // 10240 B
#define STAGE_B (2 * A_TB + B_TB)      // 20480 B (Ah, Al, Bh)
#define GEMM_SMEM (2 * STAGE_B)        // 40960 B

__device__ __forceinline__ void tile_cp_n(const f16* __restrict__ g, int ldg,
                                          int r0, int k0, uint32_t sdst,
                                          int nrows, int t) {
    int nops = nrows * 4;
    for (int o = t; o < nops; o += 128) {
        int row = o >> 2, c = o & 3;
        CP16(sdst + row * TROW + c * 16,
             g + (long long)(r0 + row) * ldg + k0 + c * 8);
    }
}

__global__ void __launch_bounds__(128, 4) gemm_2t(
    const f16* __restrict__ Ah, const f16* __restrict__ Al, int lda,
    const f16* __restrict__ Bh, int ldb,
    float* __restrict__ C, int ldc, int K)
{
    int rb = blockIdx.y, cb = blockIdx.x;
    int row0 = rb * 64, col0 = cb * 128;

    extern __shared__ char sm[];
    uint32_t sbase = smem_u32(sm);
    int t = threadIdx.x, w = t >> 5, l = t & 31;
    int wm = w & 1, wn = w >> 1;

    float acc[2][8][4];
#pragma unroll
    for (int i = 0; i < 2; i++)
#pragma unroll
        for (int j = 0; j < 8; j++)
#pragma unroll
            for (int q = 0; q < 4; q++) acc[i][j][q] = 0.f;

    int niter = K / 32;
    uint32_t stg[2] = {sbase, sbase + STAGE_B};

    tile_cp_n(Ah, lda, row0, 0, stg[0],            64,  t);
    tile_cp_n(Al, lda, row0, 0, stg[0] + A_TB,     64,  t);
    tile_cp_n(Bh, ldb, col0, 0, stg[0] + 2 * A_TB, 128, t);
    CP_COMMIT();

    int a_row = wm * 32 + (l & 15);
    int a_kb  = ((l >> 4) & 1) * 16;
    int b_row = wn * 64 + (l & 7) + ((l >> 4) & 1) * 8;
    int b_kb  = ((l >> 3) & 1) * 16;

    for (int it = 0; it < niter; it++) {
        if (it + 1 < niter) {
            uint32_t nb = stg[(it + 1) & 1];
            int k0 = (it + 1) * 32;
            tile_cp_n(Ah, lda, row0, k0, nb,            64,  t);
            tile_cp_n(Al, lda, row0, k0, nb + A_TB,     64,  t);
            tile_cp_n(Bh, ldb, col0, k0, nb + 2 * A_TB, 128, t);
            CP_COMMIT();
            CP_WAIT1();
        } else {
            CP_WAIT0();
        }
        __syncthreads();

        uint32_t base = stg[it & 1];
#pragma unroll
        for (int ks = 0; ks < 2; ks++) {
            int kbyte = ks * 32;
            uint32_t ah[2][4], al[2][4], bh[8][2];
#pragma unroll
            for (int mf = 0; mf < 2; mf++) {
                uint32_t aaddr = base + (a_row + mf * 16) * TROW + kbyte + a_kb;
                ldsm_x4(ah[mf][0], ah[mf][1], ah[mf][2], ah[mf][3], aaddr);
                ldsm_x4(al[mf][0], al[mf][1], al[mf][2], al[mf][3], aaddr + A_TB);
            }
#pragma unroll
            for (int p = 0; p < 4; p++) {
                uint32_t baddr = base + 2 * A_TB + (b_row + p * 16) * TROW + kbyte + b_kb;
                uint32_t r0, r1, r2, r3;
                ldsm_x4(r0, r1, r2, r3, baddr);
                bh[2 * p][0] = r0;     bh[2 * p][1] = r1;
                bh[2 * p + 1][0] = r2; bh[2 * p + 1][1] = r3;
            }
            // term-outer: 16 independent MMAs per sweep
#pragma unroll
            for (int mf = 0; mf < 2; mf++)
#pragma unroll
                for (int nf = 0; nf < 8; nf++) hmma(acc[mf][nf], ah[mf], bh[nf]);
#pragma unroll
            for (int mf = 0; mf < 2; mf++)
#pragma unroll
                for (int nf = 0; nf < 8; nf++) hmma(acc[mf][nf], al[mf], bh[nf]);
        }
        __syncthreads();
    }

#pragma unroll
    for (int mf = 0; mf < 2; mf++) {
        int r_lo = row0 + wm * 32 + mf * 16 + (l >> 2);
#pragma unroll
        for (int nf = 0; nf < 8; nf++) {
            int cix = col0 + wn * 64 + nf * 8 + (l & 3) * 2;
            *(float2*)&C[(long long)r_lo * ldc + cix] =
                make_float2(acc[mf][nf][0], acc[mf][nf][1]);
            *(float2*)&C[(long long)(r_lo + 8) * ldc + cix] =
                make_float2(acc[mf][nf][2], acc[mf][nf][3]);
        }
    }
}

// ---------------------------------------------------------------------------
// Fused flash attention, 2-term fp16 (Q/P split, K/V single).
// One CTA = (head, 128-row q block), heavy-first mapping.
// ---------------------------------------------------------------------------
#define FL_QROW 272
#define FL_VROW 144
#define FL_QT (128 * FL_QROW)          // 34816
#define FL_KT (64  * FL_QROW)          // 17408
#define FL_VT (128 * FL_VROW)          // 18432
#define FL_STG (FL_KT + FL_VT)         // 35840
#define FL_SMEM (2 * FL_QT + 2 * FL_STG)  // 141312

__device__ __forceinline__ void cp_rows(const f16* __restrict__ g, int ldg,
                                        int row0, int col0, uint32_t sdst,
                                        int stride, int cps_per_row, int nops, int t) {
    for (int o = t; o < nops; o += 256) {
        int r = o / cps_per_row, c = o % cps_per_row;
        CP16(sdst + r * stride + c * 16,
             g + (long long)(row0 + r) * ldg + col0 + c * 8);
    }
}

__global__ __launch_bounds__(256) void flash_k(
    const f16* __restrict__ qh, const f16* __restrict__ ql,
    const f16* __restrict__ kh, const f16* __restrict__ vth,
    f16* __restrict__ oh, f16* __restrict__ ol)
{
    int id = blockIdx.x;
    int qb = 15 - (id >> 4);           // heavy q-blocks first
    int h = id & 15;
    int kvh = h >> 2;
    int q0 = qb * 128;

    extern __shared__ char sm[];
    uint32_t S = smem_u32(sm);
    uint32_t smQ = S;
    int t = threadIdx.x, w = t >> 5, l = t & 31;
    int g = l >> 2, tg = l & 3;

    cp_rows(qh, HID, q0, h * 128, smQ,         FL_QROW, 16, 2048, t);
    cp_rows(ql, HID, q0, h * 128, smQ + FL_QT, FL_QROW, 16, 2048, t);
    {
        uint32_t st = S + 2 * FL_QT;
        cp_rows(kh, 512, 0, kvh * 128, st,            FL_QROW, 16, 1024, t);
        cp_rows(vth, S_LEN, kvh * 128, 0, st + FL_KT, FL_VROW, 8, 1024, t);
    }
    CP_COMMIT();

    float acc[16][4];
#pragma unroll
    for (int nf = 0; nf < 16; nf++)
#pragma unroll
        for (int c = 0; c < 4; c++) acc[nf][c] = 0.f;
    float m0 = -1e30f, m1 = -1e30f, l0 = 0.f, l1 = 0.f;

    int niter = 2 * qb + 2;

    int a_row = w * 16 + (l & 15);
    int a_kb  = ((l >> 4) & 1) * 16;
    int b_sub = (l & 7) + ((l >> 4) & 1) * 8;
    int b_kb  = ((l >> 3) & 1) * 16;

    for (int jj = 0; jj < niter; jj++) {
        if (jj + 1 < niter) {
            uint32_t st = S + 2 * FL_QT + ((jj + 1) & 1) * FL_STG;
            int k0 = (jj + 1) * 64;
            cp_rows(kh, 512, k0, kvh * 128, st,            FL_QROW, 16, 1024, t);
            cp_rows(vth, S_LEN, kvh * 128, k0, st + FL_KT, FL_VROW, 8, 1024, t);
            CP_COMMIT();
            CP_WAIT1();
        } else {
            CP_WAIT0();
        }
        __syncthreads();

        bool active = !(jj == 2 * qb + 1 && w < 4);
        if (active) {
            uint32_t base = S + 2 * FL_QT + (jj & 1) * FL_STG;
            uint32_t bKh = base, bVh = base + FL_KT;

            float sf[8][4];
#pragma unroll
            for (int nf = 0; nf < 8; nf++)
#pragma unroll
                for (int c = 0; c < 4; c++) sf[nf][c] = 0.f;

            // ---- S = Q K^T (2-term split) ----
#pragma unroll
            for (int ks = 0; ks < 8; ks++) {
                uint32_t aaddr = smQ + a_row * FL_QROW + ks * 32 + a_kb;
                uint32_t ah[4], al[4], bh[8][2];
                ldsm_x4(ah[0], ah[1], ah[2], ah[3], aaddr);
                ldsm_x4(al[0], al[1], al[2], al[3], aaddr + FL_QT);
#pragma unroll
                for (int p = 0; p < 4; p++) {
                    uint32_t baddr = bKh + (p * 16 + b_sub) * FL_QROW + ks * 32 + b_kb;
                    uint32_t r0, r1, r2, r3;
                    ldsm_x4(r0, r1, r2, r3, baddr);
                    bh[2 * p][0] = r0;     bh[2 * p][1] = r1;
                    bh[2 * p + 1][0] = r2; bh[2 * p + 1][1] = r3;
                }
#pragma unroll
                for (int nf = 0; nf < 8; nf++) hmma(sf[nf], ah, bh[nf]);
#pragma unroll
                for (int nf = 0; nf < 8; nf++) hmma(sf[nf], al, bh[nf]);
            }

            // ---- causal mask (diag blocks only) ----
            if (jj >= 2 * qb) {
                int r0g = q0 + w * 16 + g;
#pragma unroll
                for (int nf = 0; nf < 8; nf++) {
                    int cg = jj * 64 + nf * 8 + 2 * tg;
                    if (cg     > r0g)     sf[nf][0] = -1e30f;
                    if (cg + 1 > r0g)     sf[nf][1] = -1e30f;
                    if (cg     > r0g + 8) sf[nf][2] = -1e30f;
                    if (cg + 1 > r0g + 8) sf[nf][3] = -1e30f;
                }
            }

            // ---- online softmax (base-2) ----
            float mx0 = m0, mx1 = m1;
#pragma unroll
            for (int nf = 0; nf < 8; nf++) {
                mx0 = fmaxf(mx0, fmaxf(sf[nf][0], sf[nf][1]));
                mx1 = fmaxf(mx1, fmaxf(sf[nf][2], sf[nf][3]));
            }
            mx0 = fmaxf(mx0, __shfl_xor_sync(0xffffffffu, mx0, 1));
            mx0 = fmaxf(mx0, __shfl_xor_sync(0xffffffffu, mx0, 2));
            mx1 = fmaxf(mx1, __shfl_xor_sync(0xffffffffu, mx1, 1));
            mx1 = fmaxf(mx1, __shfl_xor_sync(0xffffffffu, mx1, 2));
            float al0 = ex2(m0 - mx0), al1 = ex2(m1 - mx1);
            m0 = mx0; m1 = mx1;
            l0 *= al0; l1 *= al1;
#pragma unroll
            for (int nf = 0; nf < 8; nf++) {
                float p0 = ex2(sf[nf][0] - m0);
                float p1 = ex2(sf[nf][1] - m0);
                float p2 = ex2(sf[nf][2] - m1);
                float p3 = ex2(sf[nf][3] - m1);
                sf[nf][0] = p0; sf[nf][1] = p1; sf[nf][2] = p2; sf[nf][3] = p3;
                l0 += p0 + p1; l1 += p2 + p3;
            }
#pragma unroll
            for (int nf = 0; nf < 16; nf++) {
                acc[nf][0] *= al0; acc[nf][1] *= al0;
                acc[nf][2] *= al1; acc[nf][3] *= al1;
            }

            // ---- PV: acc += (Ph+Pl) V, P split in registers ----
#pragma unroll
            for (int u = 0; u < 4; u++) {
                uint32_t ph[4], pl[4];
#pragma unroll
                for (int q = 0; q < 4; q++) {
                    float e0 = sf[2 * u + (q >> 1)][(q & 1) ? 2 : 0];
                    float e1 = sf[2 * u + (q >> 1)][(q & 1) ? 3 : 1];
                    uint32_t hw = pack_f16(e0, e1);
                    float2 hf = unpack_f16(hw);
                    ph[q] = hw;
                    pl[q] = pack_f16(e0 - hf.x, e1 - hf.y);
                }
                // reorder to A-fragment order: {r0c0, r8c0, r0c1, r8c1}
                uint32_t pA_h[4] = {ph[0], ph[1], ph[2], ph[3]};
                uint32_t pA_l[4] = {pl[0], pl[1], pl[2], pl[3]};
#pragma unroll
                for (int p = 0; p < 8; p++) {
                    uint32_t vaddr = bVh + (p * 16 + b_sub) * FL_VROW + u * 32 + b_kb;
                    uint32_t r0, r1, r2, r3;
                    ldsm_x4(r0, r1, r2, r3, vaddr);
                    uint32_t vh0[2] = {r0, r1}, vh1[2] = {r2, r3};
                    hmma(acc[2 * p],     pA_h, vh0);
                    hmma(acc[2 * p + 1], pA_h, vh1);
                    hmma(acc[2 * p],     pA_l, vh0);
                    hmma(acc[2 * p + 1], pA_l, vh1);
                }
            }
        }
        __syncthreads();
    }

    l0 += __shfl_xor_sync(0xffffffffu, l0, 1);
    l0 += __shfl_xor_sync(0xffffffffu, l0, 2);
    l1 += __shfl_xor_sync(0xffffffffu, l1, 1);
    l1 += __shfl_xor_sync(0xffffffffu, l1, 2);
    float i0 = 1.f / l0, i1 = 1.f / l1;
    int row0 = q0 + w * 16 + g;
#pragma unroll
    for (int nf = 0; nf < 16; nf++) {
        int col = h * 128 + nf * 8 + 2 * tg;
        float o0 = acc[nf][0] * i0, o1 = acc[nf][1] * i0;
        float o2 = acc[nf][2] * i1, o3 = acc[nf][3] * i1;
        uint32_t hw0 = pack_f16(o0, o1);
        uint32_t hw1 = pack_f16(o2, o3);
        float2 f0 = unpack_f16(hw0);
        float2 f1 = unpack_f16(hw1);
        uint32_t lw0 = pack_f16(o0 - f0.x, o1 - f0.y);
        uint32_t lw1 = pack_f16(o2 - f1.x, o3 - f1.y);
        *(uint32_t*)&oh[(long long)row0 * HID + col]       = hw0;
        *(uint32_t*)&ol[(long long)row0 * HID + col]       = lw0;
        *(uint32_t*)&oh[(long long)(row0 + 8) * HID + col] = hw1;
        *(uint32_t*)&ol[(long long)(row0 + 8) * HID + col] = lw1;
    }
}

// ---------------------------------------------------------------------------
__global__ __launch_bounds__(256) void conv_k(const float* __restrict__ x,
                                              f16* __restrict__ h, f16* __restrict__ l, int n)
{
    int i = blockIdx.x * 256 + threadIdx.x;
    if (i >= n) return;
    float v = x[i];
    f16 a = __float2half_rn(v);
    h[i] = a;
    l[i] = __float2half_rn(v - __half2float(a));
}

// transpose + single fp16: dst[r][c] = src[c][scol0 + r]
__global__ __launch_bounds__(256) void transconv1_k(const float* __restrict__ src, int sld,
                                                    int scol0, f16* __restrict__ dh, int dld)
{
    __shared__ float tile[32][33];
    int tx = threadIdx.x, ty = threadIdx.y;
    int sr = blockIdx.x * 32;
    int sc = blockIdx.y * 32;
#pragma unroll
    for (int k = 0; k < 32; k += 8)
        tile[ty + k][tx] = src[(long long)(sr + ty + k) * sld + scol0 + sc + tx];
    __syncthreads();
#pragma unroll
    for (int k = 0; k < 32; k += 8) {
        long long o = (long long)(sc + ty + k) * dld + sr + tx;
        dh[o] = __float2half_rn(tile[tx][ty + k]);
    }
}

__global__ __launch_bounds__(256) void rope_split_k(const float* __restrict__ qkv,
    f16* __restrict__ qh, f16* __restrict__ ql, f16* __restrict__ kh)
{
    int idx = blockIdx.x * 256 + threadIdx.x;
    int i  = idx & 63;
    int hh = (idx >> 6) % 20;
    int s  = idx / (64 * 20);
    const float* p = qkv + (long long)s * QKV_N + ((hh < 16) ? hh * 128 : 2048 + (hh - 16) * 128);

    float f  = (float)s * __expf((float)i * -0.14391156831212787f);
    float sf = sinf(f), cf = cosf(f);
    float x1 = p[i], x2 = p[i + 64];
    float y1 = x1 * cosf(sf) - x2 * sinf(sf);
    float y2 = x2 * cosf(cf) + x1 * sinf(cf);

    if (hh < 16) {
        y1 *= QSCALE; y2 *= QSCALE;
        long long o = (long long)s * HID + hh * 128 + i;
        f16 a = __float2half_rn(y1);
        qh[o] = a; ql[o] = __float2half_rn(y1 - __half2float(a));
        f16 b = __float2half_rn(y2);
        qh[o + 64] = b; ql[o + 64] = __float2half_rn(y2 - __half2float(b));
    } else {
        long long o = (long long)s * 512 + (hh - 16) * 128 + i;
        kh[o]      = __float2half_rn(y1);
        kh[o + 64] = __float2half_rn(y2);
    }
}

// ---------------------------------------------------------------------------
extern "C" void kernel_launch(void* const* d_in, const int* in_sizes, int n_in,
                              void* d_out, int out_size)
{
    const float* hidden = (const float*)d_in[0];
    const float* W_attn = (const float*)d_in[3];
    const float* W_proj = (const float*)d_in[4];
    float* out = (float*)d_out;

    float* qkv;
    f16 *xh, *xl, *wh, *w2h, *qh, *ql, *kh, *vth;
    cudaGetSymbolAddress((void**)&qkv, g_qkv);
    cudaGetSymbolAddress((void**)&xh, g_xh);   cudaGetSymbolAddress((void**)&xl, g_xl);
    cudaGetSymbolAddress((void**)&wh, g_wh);   cudaGetSymbolAddress((void**)&w2h, g_w2h);
    cudaGetSymbolAddress((void**)&qh, g_qh);   cudaGetSymbolAddress((void**)&ql, g_ql);
    cudaGetSymbolAddress((void**)&kh, g_kh);   cudaGetSymbolAddress((void**)&vth, g_vth);

    cudaFuncSetAttribute(gemm_2t, cudaFuncAttributeMaxDynamicSharedMemorySize, GEMM_SMEM);
    cudaFuncSetAttribute(flash_k, cudaFuncAttributeMaxDynamicSharedMemorySize, FL_SMEM);

    // 1) splits
    conv_k<<<(S_LEN * HID) / 256, 256>>>(hidden, xh, xl, S_LEN * HID);
    transconv1_k<<<dim3(64, 96), dim3(32, 8)>>>(W_attn, QKV_N, 0, wh, HID);
    transconv1_k<<<dim3(64, 64), dim3(32, 8)>>>(W_proj, HID, 0, w2h, HID);

    // 2) qkv = hidden @ W_attn
    gemm_2t<<<dim3(QKV_N / 128, S_LEN / 64), 128, GEMM_SMEM>>>(
        xh, xl, HID, wh, HID, qkv, QKV_N, HID);

    // 3) rope + split q, single k ; transpose v
    rope_split_k<<<(S_LEN * 20 * 64) / 256, 256>>>(qkv, qh, ql, kh);
    transconv1_k<<<dim3(64, 16), dim3(32, 8)>>>(qkv, QKV_N, 2560, vth, S_LEN);

    // 4) fused flash attention -> split fp16 attn (xh, xl)
    flash_k<<<256, 256, FL_SMEM>>>(qh, ql, kh, vth, xh, xl);

    // 5) out = attn @ W_proj
    gemm_2t<<<dim3(HID / 128, S_LEN / 64), 128, GEMM_SMEM>>>(
        xh, xl, HID, w2h, HID, out, HID, HID);
}